// round 2
// baseline (speedup 1.0000x reference)
#include <cuda_runtime.h>
#include <cuda_bf16.h>
#include <cstdint>

// ---------------- problem constants ----------------
#define Bn   64
#define Tn   256
#define En   128
#define H1   256          // U1
#define H2   256          // U2
#define U3n  512
#define U4n  5000
#define ROWS (Bn*Tn)      // 16384

// ---------------- scratch (device globals; no allocation) ----------------
__device__ float g_Z1f[ROWS * 4*H1];   // 64 MB
__device__ float g_Z1b[ROWS * 4*H1];   // 64 MB
__device__ float g_HS [ROWS * 2*H1];   // 32 MB  (fw cols 0..255, bw cols 256..511)
__device__ float g_Z2 [ROWS * 4*H2];   // 64 MB
__device__ float g_HL [Bn * H2];
__device__ float g_D3 [Bn * U3n];

// ---------------- small PTX helpers ----------------
__device__ __forceinline__ unsigned ctarank() {
    unsigned r; asm("mov.u32 %0, %%cluster_ctarank;" : "=r"(r)); return r;
}
__device__ __forceinline__ void cluster_sync_all() {
    asm volatile("barrier.cluster.arrive.aligned;\n\tbarrier.cluster.wait.aligned;" ::: "memory");
}
__device__ __forceinline__ void st_cluster_f32(unsigned local_addr, unsigned rank, float v) {
    unsigned ra;
    asm volatile("mapa.shared::cluster.u32 %0, %1, %2;" : "=r"(ra) : "r"(local_addr), "r"(rank));
    asm volatile("st.shared::cluster.f32 [%0], %1;" :: "r"(ra), "f"(v) : "memory");
}
__device__ __forceinline__ unsigned f2tf32(float x) {
    unsigned r; asm("cvt.rna.tf32.f32 %0, %1;" : "=r"(r) : "f"(x)); return r;
}
__device__ __forceinline__ void mma_tf32(float& d0, float& d1, float& d2, float& d3,
                                         unsigned a0, unsigned a1, unsigned a2, unsigned a3,
                                         unsigned b0, unsigned b1) {
    asm volatile("mma.sync.aligned.m16n8k8.row.col.f32.tf32.tf32.f32 "
                 "{%0,%1,%2,%3},{%4,%5,%6,%7},{%8,%9},{%0,%1,%2,%3};"
                 : "+f"(d0), "+f"(d1), "+f"(d2), "+f"(d3)
                 : "r"(a0), "r"(a1), "r"(a2), "r"(a3), "r"(b0), "r"(b1));
}
__device__ __forceinline__ float sigmoidf_(float z) {
    return 1.0f / (1.0f + __expf(-z));
}

// =====================================================================
// Generic tf32 tensor-core GEMM:  C[M,N] = gather(A)[M,K] * B[K,N] + bias
// A row-major (lda), B row-major (ldb=N), C row-major (N).
// BM=128, BN=128, BK=16, 256 threads, warp grid 2x4, warp tile 64x32.
// K must be a multiple of 16. M,N arbitrary (guarded).
// =====================================================================
__global__ __launch_bounds__(256) void gemm_tf32(
    const float* __restrict__ A, const float* __restrict__ B,
    const float* __restrict__ bias, float* __restrict__ C,
    const int* __restrict__ gather,
    int M, int N, int K, int lda, int do_relu)
{
    __shared__ float As[128][17];
    __shared__ float Bs[16][129];

    const int bm = blockIdx.y * 128;
    const int bn = blockIdx.x * 128;
    const int tid = threadIdx.x;
    const int warp = tid >> 5, lane = tid & 31;
    const int wm = warp >> 2, wn = warp & 3;          // 2 x 4 warp grid
    const int mBase = wm * 64, nBase = wn * 32;       // warp tile 64x32
    const int grp = lane >> 2, tig = lane & 3;

    float acc[4][4][4];
#pragma unroll
    for (int a = 0; a < 4; a++)
#pragma unroll
        for (int b = 0; b < 4; b++)
#pragma unroll
            for (int c = 0; c < 4; c++) acc[a][b][c] = 0.f;

    for (int kb = 0; kb < K; kb += 16) {
        // ---- load A tile (128 x 16) ----
#pragma unroll
        for (int i = 0; i < 2; i++) {
            int idx = tid * 2 + i;            // 0..511
            int row = idx >> 2;               // 0..127
            int f4  = (idx & 3) << 2;         // 0,4,8,12
            int R = bm + row;
            float4 v = make_float4(0.f, 0.f, 0.f, 0.f);
            if (R < M) {
                long ar = gather ? (long)gather[R] : (long)R;
                v = *(const float4*)&A[ar * (long)lda + kb + f4];
            }
            As[row][f4 + 0] = __uint_as_float(f2tf32(v.x));
            As[row][f4 + 1] = __uint_as_float(f2tf32(v.y));
            As[row][f4 + 2] = __uint_as_float(f2tf32(v.z));
            As[row][f4 + 3] = __uint_as_float(f2tf32(v.w));
        }
        // ---- load B tile (16 x 128) ----
#pragma unroll
        for (int i = 0; i < 2; i++) {
            int idx = tid * 2 + i;            // 0..511
            int krow = idx >> 5;              // 0..15
            int c4 = (idx & 31) << 2;         // 0..124
            int gc = bn + c4;
            const float* bp = &B[(long)(kb + krow) * N + gc];
            float4 v = make_float4(0.f, 0.f, 0.f, 0.f);
            if (gc + 3 < N) v = *(const float4*)bp;
            else {
                if (gc + 0 < N) v.x = bp[0];
                if (gc + 1 < N) v.y = bp[1];
                if (gc + 2 < N) v.z = bp[2];
            }
            Bs[krow][c4 + 0] = __uint_as_float(f2tf32(v.x));
            Bs[krow][c4 + 1] = __uint_as_float(f2tf32(v.y));
            Bs[krow][c4 + 2] = __uint_as_float(f2tf32(v.z));
            Bs[krow][c4 + 3] = __uint_as_float(f2tf32(v.w));
        }
        __syncthreads();

        // ---- compute: two k8 steps ----
#pragma unroll
        for (int ks = 0; ks < 16; ks += 8) {
            unsigned afrag[4][4];
#pragma unroll
            for (int mi = 0; mi < 4; mi++) {
                int m0 = mBase + mi * 16;
                afrag[mi][0] = __float_as_uint(As[m0 + grp    ][ks + tig    ]);
                afrag[mi][1] = __float_as_uint(As[m0 + grp + 8][ks + tig    ]);
                afrag[mi][2] = __float_as_uint(As[m0 + grp    ][ks + tig + 4]);
                afrag[mi][3] = __float_as_uint(As[m0 + grp + 8][ks + tig + 4]);
            }
#pragma unroll
            for (int ni = 0; ni < 4; ni++) {
                int n0 = nBase + ni * 8 + grp;
                unsigned b0 = __float_as_uint(Bs[ks + tig    ][n0]);
                unsigned b1 = __float_as_uint(Bs[ks + tig + 4][n0]);
#pragma unroll
                for (int mi = 0; mi < 4; mi++)
                    mma_tf32(acc[mi][ni][0], acc[mi][ni][1], acc[mi][ni][2], acc[mi][ni][3],
                             afrag[mi][0], afrag[mi][1], afrag[mi][2], afrag[mi][3], b0, b1);
            }
        }
        __syncthreads();
    }

    // ---- epilogue ----
#pragma unroll
    for (int mi = 0; mi < 4; mi++) {
#pragma unroll
        for (int ni = 0; ni < 4; ni++) {
            int r0 = bm + mBase + mi * 16 + grp;
            int c0 = bn + nBase + ni * 8 + tig * 2;
            float bv0 = (bias && c0     < N) ? bias[c0]     : 0.f;
            float bv1 = (bias && c0 + 1 < N) ? bias[c0 + 1] : 0.f;
            float o0 = acc[mi][ni][0] + bv0;
            float o1 = acc[mi][ni][1] + bv1;
            float o2 = acc[mi][ni][2] + bv0;
            float o3 = acc[mi][ni][3] + bv1;
            if (do_relu) {
                o0 = fmaxf(o0, 0.f); o1 = fmaxf(o1, 0.f);
                o2 = fmaxf(o2, 0.f); o3 = fmaxf(o3, 0.f);
            }
            if (r0 < M) {
                if (c0     < N) C[(long)r0 * N + c0]     = o0;
                if (c0 + 1 < N) C[(long)r0 * N + c0 + 1] = o1;
            }
            int r1 = r0 + 8;
            if (r1 < M) {
                if (c0     < N) C[(long)r1 * N + c0]     = o2;
                if (c0 + 1 < N) C[(long)r1 * N + c0 + 1] = o3;
            }
        }
    }
}

// =====================================================================
// LSTM recurrence, cluster of 8 CTAs, 256 threads/CTA.
// Rank r owns 32 hidden units (r*32..r*32+31) for all 4 gates.
// SMEM: Usl[256][128] (k-major, gate-interleaved cols) + double-buffered
// h[2][BSUB][257] + z partials[2][BSUB][128].
// One barrier.cluster per step; h pushed to all 8 ranks via st.shared::cluster.
// =====================================================================
template<int BSUB, bool WRITE_HS>
__device__ __forceinline__ void lstm_body(
    const float* __restrict__ Z,    // [ROWS,1024], bias already folded in
    const float* __restrict__ U,    // [256,1024]
    float* __restrict__ OUT,        // HS [ROWS,512] or HL [64,256]
    int sbase, int dir)
{
    extern __shared__ float smem[];
    float* Usl   = smem;                          // 32768 floats
    float* hbuf  = smem + 32768;                  // 2*BSUB*257
    float* zpart = hbuf + 2 * BSUB * 257;         // 2*BSUB*128

    const int tid = threadIdx.x;
    const unsigned r = ctarank();

    // load U slice: Usl[k*128 + j], j -> global col g*256 + r*32 + u
    for (int idx = tid; idx < 256 * 128; idx += 256) {
        int k = idx >> 7, j = idx & 127;
        int g = j >> 5, u = j & 31;
        Usl[idx] = U[k * 1024 + g * 256 + (int)r * 32 + u];
    }
    // zero h buffer 0
    for (int idx = tid; idx < BSUB * 257; idx += 256) hbuf[idx] = 0.f;
    __syncthreads();

    // matvec thread mapping
    const int warp = tid >> 5, lane = tid & 31;
    const int ws = warp >> 2;                 // k-split: 0 -> k[0,128), 1 -> k[128,256)
    const int wi = warp & 3;
    const int cg = lane & 7;
    const int sgi = lane >> 3;
    const int SPG = BSUB / 4;                 // samples per thread (2 or 1)
    const int j4 = wi * 8 + cg;               // column group: cols j4*4 .. +4
    const int s_base = sgi * SPG;
    const int k0 = ws * 128;

    // cell-update mapping
    const bool is_cell = (tid < BSUB * 32);
    const int cs = tid >> 5;                  // sample within cluster chunk
    const int cu = tid & 31;                  // unit within rank's 32
    const unsigned smem_u32 = (unsigned)__cvta_generic_to_shared(smem);
    const unsigned hbase_u32 = smem_u32 + 32768u * 4u;

    float cstate = 0.f;
    int cur = 0;

    for (int step = 0; step < Tn; ++step) {
        const int t = dir ? (Tn - 1 - step) : step;

        // prefetch this step's z_in (latency hides under the matvec)
        float zin[4];
        if (is_cell) {
            const float* zr = Z + ((long)(sbase + cs) * Tn + t) * 1024 + (int)r * 32 + cu;
#pragma unroll
            for (int g = 0; g < 4; g++) zin[g] = zr[g * 256];
        }

        // ---- matvec: z[s, j] += h[s,:] @ Usl[:, j] over this warpset's k range ----
        float acc[SPG * 4];
#pragma unroll
        for (int i = 0; i < SPG * 4; i++) acc[i] = 0.f;
        const float* hb = hbuf + cur * (BSUB * 257);
#pragma unroll 4
        for (int kk = 0; kk < 128; kk++) {
            int k = k0 + kk;
            float4 u4 = *(const float4*)&Usl[(k << 7) + (j4 << 2)];
#pragma unroll
            for (int sp = 0; sp < SPG; sp++) {
                float hv = hb[(s_base + sp) * 257 + k];
                acc[sp * 4 + 0] = fmaf(u4.x, hv, acc[sp * 4 + 0]);
                acc[sp * 4 + 1] = fmaf(u4.y, hv, acc[sp * 4 + 1]);
                acc[sp * 4 + 2] = fmaf(u4.z, hv, acc[sp * 4 + 2]);
                acc[sp * 4 + 3] = fmaf(u4.w, hv, acc[sp * 4 + 3]);
            }
        }
        // store partials
#pragma unroll
        for (int sp = 0; sp < SPG; sp++) {
            float4 v = make_float4(acc[sp * 4 + 0], acc[sp * 4 + 1], acc[sp * 4 + 2], acc[sp * 4 + 3]);
            *(float4*)&zpart[ws * (BSUB * 128) + (s_base + sp) * 128 + (j4 << 2)] = v;
        }
        __syncthreads();

        // ---- cell update ----
        if (is_cell) {
            float zv[4];
#pragma unroll
            for (int g = 0; g < 4; g++) {
                int j = g * 32 + cu;
                zv[g] = zpart[cs * 128 + j] + zpart[BSUB * 128 + cs * 128 + j] + zin[g];
            }
            float ig = sigmoidf_(zv[0]);
            float fg = sigmoidf_(zv[1]);
            float gg = fmaxf(zv[2], 0.f);
            float og = sigmoidf_(zv[3]);
            cstate = fg * cstate + ig * gg;
            float hval = og * fmaxf(cstate, 0.f);

            // push h slice to all 8 ranks' next buffer
            int nxt = cur ^ 1;
            unsigned loff = hbase_u32 + (unsigned)(nxt * (BSUB * 257) + cs * 257 + (int)r * 32 + cu) * 4u;
#pragma unroll
            for (unsigned tr = 0; tr < 8; tr++) st_cluster_f32(loff, tr, hval);

            if (WRITE_HS) {
                OUT[((long)(sbase + cs) * Tn + t) * (2 * H1) + dir * H1 + (int)r * 32 + cu] = hval;
            } else if (step == Tn - 1) {
                OUT[(long)(sbase + cs) * H2 + (int)r * 32 + cu] = hval;
            }
        }
        cluster_sync_all();
        cur ^= 1;
    }
}

__global__ void __cluster_dims__(8, 1, 1) __launch_bounds__(256, 1)
lstm1_kernel(const float* __restrict__ Zf, const float* __restrict__ Zb,
             const float* __restrict__ Uf, const float* __restrict__ Ub,
             float* __restrict__ HS)
{
    int cid = blockIdx.x >> 3;          // 0..15
    int dir = cid >> 3;                 // 0: fw (clusters 0..7), 1: bw (8..15)
    int cl  = cid & 7;
    lstm_body<8, true>(dir ? Zb : Zf, dir ? Ub : Uf, HS, cl * 8, dir);
}

__global__ void __cluster_dims__(8, 1, 1) __launch_bounds__(256, 1)
lstm2_kernel(const float* __restrict__ Z, const float* __restrict__ U,
             float* __restrict__ HL)
{
    int cid = blockIdx.x >> 3;          // 0..15
    lstm_body<4, false>(Z, U, HL, cid * 4, 0);
}

// =====================================================================
// Dense head
// =====================================================================
__global__ __launch_bounds__(256) void dense3_kernel(
    const float* __restrict__ HL, const float* __restrict__ W3,
    const float* __restrict__ b3, float* __restrict__ D3)
{
    __shared__ float h[256];
    int s = blockIdx.x;
    h[threadIdx.x] = HL[s * 256 + threadIdx.x];
    __syncthreads();
    for (int j = threadIdx.x; j < U3n; j += 256) {
        float acc = b3[j];
#pragma unroll 8
        for (int k = 0; k < 256; k++) acc = fmaf(h[k], W3[k * U3n + j], acc);
        D3[s * U3n + j] = fmaxf(acc, 0.f);
    }
}

__global__ __launch_bounds__(256) void softmax_kernel(float* __restrict__ X)
{
    __shared__ float red[256];
    float* x = X + (long)blockIdx.x * U4n;
    int tid = threadIdx.x;

    float m = -1e30f;
    for (int j = tid; j < U4n; j += 256) m = fmaxf(m, x[j]);
    red[tid] = m; __syncthreads();
    for (int s = 128; s > 0; s >>= 1) {
        if (tid < s) red[tid] = fmaxf(red[tid], red[tid + s]);
        __syncthreads();
    }
    m = red[0]; __syncthreads();

    float sum = 0.f;
    for (int j = tid; j < U4n; j += 256) {
        float e = __expf(x[j] - m);
        x[j] = e;
        sum += e;
    }
    red[tid] = sum; __syncthreads();
    for (int s = 128; s > 0; s >>= 1) {
        if (tid < s) red[tid] += red[tid + s];
        __syncthreads();
    }
    float inv = 1.f / red[0];
    __syncthreads();
    for (int j = tid; j < U4n; j += 256) x[j] *= inv;
}

// =====================================================================
// launcher
// =====================================================================
extern "C" void kernel_launch(void* const* d_in, const int* in_sizes, int n_in,
                              void* d_out, int out_size)
{
    const int*   tokens = (const int*)  d_in[0];
    const float* emb    = (const float*)d_in[1];
    const float* W1f    = (const float*)d_in[2];
    const float* U1f    = (const float*)d_in[3];
    const float* b1f    = (const float*)d_in[4];
    const float* W1b    = (const float*)d_in[5];
    const float* U1b    = (const float*)d_in[6];
    const float* b1b    = (const float*)d_in[7];
    const float* W2     = (const float*)d_in[8];
    const float* U2m    = (const float*)d_in[9];
    const float* b2     = (const float*)d_in[10];
    const float* W3     = (const float*)d_in[11];
    const float* b3     = (const float*)d_in[12];
    const float* W4     = (const float*)d_in[13];
    const float* b4     = (const float*)d_in[14];
    float* out = (float*)d_out;

    float *Z1f, *Z1b, *HS, *Z2, *HL, *D3;
    cudaGetSymbolAddress((void**)&Z1f, g_Z1f);
    cudaGetSymbolAddress((void**)&Z1b, g_Z1b);
    cudaGetSymbolAddress((void**)&HS,  g_HS);
    cudaGetSymbolAddress((void**)&Z2,  g_Z2);
    cudaGetSymbolAddress((void**)&HL,  g_HL);
    cudaGetSymbolAddress((void**)&D3,  g_D3);

    const int smem1 = (32768 + 2 * 8 * 257 + 2 * 8 * 128) * 4;   // 155712
    const int smem2 = (32768 + 2 * 4 * 257 + 2 * 4 * 128) * 4;   // 143392
    cudaFuncSetAttribute((const void*)lstm1_kernel,
                         cudaFuncAttributeMaxDynamicSharedMemorySize, smem1);
    cudaFuncSetAttribute((const void*)lstm2_kernel,
                         cudaFuncAttributeMaxDynamicSharedMemorySize, smem2);

    // 1) embedding gather + LSTM1 input projections (bias folded)
    {
        dim3 grid(4 * H1 / 128, ROWS / 128);   // (8, 128)
        gemm_tf32<<<grid, 256>>>(emb, W1f, b1f, Z1f, tokens, ROWS, 4 * H1, En, En, 0);
        gemm_tf32<<<grid, 256>>>(emb, W1b, b1b, Z1b, tokens, ROWS, 4 * H1, En, En, 0);
    }
    // 2) BiLSTM layer 1 (both directions)
    lstm1_kernel<<<128, 256, smem1>>>(Z1f, Z1b, U1f, U1b, HS);
    // 3) LSTM2 input projection
    {
        dim3 grid(4 * H2 / 128, ROWS / 128);
        gemm_tf32<<<grid, 256>>>(HS, W2, b2, Z2, nullptr, ROWS, 4 * H2, 2 * H1, 2 * H1, 0);
    }
    // 4) LSTM2 (h_last only)
    lstm2_kernel<<<128, 256, smem2>>>(Z2, U2m, HL);
    // 5) dense relu
    dense3_kernel<<<Bn, 256>>>(HL, W3, b3, D3);
    // 6) logits GEMM into d_out
    {
        dim3 grid((U4n + 127) / 128, 1);
        gemm_tf32<<<grid, 256>>>(D3, W4, b4, out, nullptr, Bn, U4n, U3n, U3n, 0);
    }
    // 7) softmax in place
    softmax_kernel<<<Bn, 256>>>(out);
}

// round 3
// speedup vs baseline: 2.2007x; 2.2007x over previous
#include <cuda_runtime.h>
#include <cuda_bf16.h>
#include <cstdint>

typedef unsigned int uint;

// ---------------- problem constants ----------------
#define Bn   64
#define Tn   256
#define En   128
#define H1   256
#define H2   256
#define U3n  512
#define U4n  5000
#define ROWS (Bn*Tn)      // 16384

// ---------------- scratch ----------------
__device__ float g_Z1f[ROWS * 4*H1];
__device__ float g_Z1b[ROWS * 4*H1];
__device__ __nv_bfloat16 g_HS[ROWS * 2*H1];
__device__ float g_Z2 [ROWS * 4*H2];
__device__ float g_HL [Bn * H2];
__device__ float g_D3 [Bn * U3n];

// ---------------- helpers ----------------
__device__ __forceinline__ unsigned ctarank() {
    unsigned r; asm("mov.u32 %0, %%cluster_ctarank;" : "=r"(r)); return r;
}
__device__ __forceinline__ void cluster_sync_all() {
    asm volatile("barrier.cluster.arrive.aligned;\n\tbarrier.cluster.wait.aligned;" ::: "memory");
}
__device__ __forceinline__ void st_cluster_u32(unsigned local_addr, unsigned rank, uint v) {
    unsigned ra;
    asm volatile("mapa.shared::cluster.u32 %0, %1, %2;" : "=r"(ra) : "r"(local_addr), "r"(rank));
    asm volatile("st.shared::cluster.b32 [%0], %1;" :: "r"(ra), "r"(v) : "memory");
}
__device__ __forceinline__ uint pack2bf(float a, float b) {
    __nv_bfloat162 t = __floats2bfloat162_rn(a, b);
    return *(uint*)&t;
}
__device__ __forceinline__ void mma_bf16(float* d,
                                         uint a0, uint a1, uint a2, uint a3,
                                         uint b0, uint b1) {
    asm volatile("mma.sync.aligned.m16n8k16.row.col.f32.bf16.bf16.f32 "
                 "{%0,%1,%2,%3},{%4,%5,%6,%7},{%8,%9},{%0,%1,%2,%3};"
                 : "+f"(d[0]), "+f"(d[1]), "+f"(d[2]), "+f"(d[3])
                 : "r"(a0), "r"(a1), "r"(a2), "r"(a3), "r"(b0), "r"(b1));
}
__device__ __forceinline__ float sigmoidf_(float z) {
    return 1.0f / (1.0f + __expf(-z));
}

// =====================================================================
// bf16 tensor-core GEMM:  C[M,N] = gather(A)[M,K] * B[K,N] + bias
// A fp32 or bf16 (row-major, lda), B fp32 row-major [K,N], C fp32.
// BM=128, BN=128, BK=32, 256 threads, warp grid 2x4, warp tile 64x32.
// K % 32 == 0. M, N arbitrary (guarded).
// =====================================================================
__global__ __launch_bounds__(256) void gemm_bf16(
    const void* __restrict__ A, int a_bf16,
    const float* __restrict__ B, const float* __restrict__ bias,
    float* __restrict__ C, const int* __restrict__ gather,
    int M, int N, int K, int lda)
{
    // As16[m][k], rows padded to 40 u16 (80B) -> conflict-free frag loads
    __shared__ __align__(16) unsigned short As16[128][40];
    // Bsu[n][k/2] packed bf16 pairs along k, padded to 20 u32
    __shared__ __align__(16) uint Bsu[128][20];

    const int bm = blockIdx.y * 128;
    const int bn = blockIdx.x * 128;
    const int tid = threadIdx.x;
    const int warp = tid >> 5, lane = tid & 31;
    const int wm = warp >> 2, wn = warp & 3;
    const int mBase = wm * 64, nBase = wn * 32;
    const int grp = lane >> 2, tig = lane & 3;

    float acc[4][4][4];
#pragma unroll
    for (int a = 0; a < 4; a++)
#pragma unroll
        for (int b = 0; b < 4; b++)
#pragma unroll
            for (int c = 0; c < 4; c++) acc[a][b][c] = 0.f;

    for (int kb = 0; kb < K; kb += 32) {
        // ---- stage A tile (128 x 32) ----
#pragma unroll
        for (int i = 0; i < 4; i++) {
            int g = tid + i * 256;           // 0..1023
            int row = g >> 3;
            int kq  = (g & 7) << 2;          // 0,4,...,28
            int R = bm + row;
            uint2 w = make_uint2(0u, 0u);
            if (R < M) {
                long ar = gather ? (long)gather[R] : (long)R;
                if (a_bf16) {
                    w = *(const uint2*)((const __nv_bfloat16*)A + ar * (long)lda + kb + kq);
                } else {
                    float4 v = *(const float4*)((const float*)A + ar * (long)lda + kb + kq);
                    w.x = pack2bf(v.x, v.y);
                    w.y = pack2bf(v.z, v.w);
                }
            }
            *(uint2*)&As16[row][kq] = w;
        }
        // ---- stage B tile (32 x 128), transposed to k-pair packing ----
        unsigned short* bs = (unsigned short*)&Bsu[0][0];
#pragma unroll
        for (int i = 0; i < 4; i++) {
            int g = tid + i * 256;           // 0..1023
            int krow = g >> 5;               // 0..31
            int nq = (g & 31) << 2;
            int gc = bn + nq;
            const float* bp = &B[(long)(kb + krow) * N + gc];
            float4 v = make_float4(0.f, 0.f, 0.f, 0.f);
            if (gc + 3 < N) v = *(const float4*)bp;
            else {
                if (gc + 0 < N) v.x = bp[0];
                if (gc + 1 < N) v.y = bp[1];
                if (gc + 2 < N) v.z = bp[2];
            }
            bs[(nq + 0) * 40 + krow] = __bfloat16_as_ushort(__float2bfloat16_rn(v.x));
            bs[(nq + 1) * 40 + krow] = __bfloat16_as_ushort(__float2bfloat16_rn(v.y));
            bs[(nq + 2) * 40 + krow] = __bfloat16_as_ushort(__float2bfloat16_rn(v.z));
            bs[(nq + 3) * 40 + krow] = __bfloat16_as_ushort(__float2bfloat16_rn(v.w));
        }
        __syncthreads();

        // ---- compute: two k16 steps ----
        const uint* ap = (const uint*)&As16[0][0];   // row stride 20 words
#pragma unroll
        for (int kt = 0; kt < 2; kt++) {
            int w0 = kt * 8 + tig;
            uint afr[4][4];
#pragma unroll
            for (int mi = 0; mi < 4; mi++) {
                int m0 = mBase + mi * 16;
                afr[mi][0] = ap[(m0 + grp    ) * 20 + w0];
                afr[mi][1] = ap[(m0 + grp + 8) * 20 + w0];
                afr[mi][2] = ap[(m0 + grp    ) * 20 + w0 + 4];
                afr[mi][3] = ap[(m0 + grp + 8) * 20 + w0 + 4];
            }
#pragma unroll
            for (int ni = 0; ni < 4; ni++) {
                int n = nBase + ni * 8 + grp;
                uint b0 = Bsu[n][w0];
                uint b1 = Bsu[n][w0 + 4];
#pragma unroll
                for (int mi = 0; mi < 4; mi++)
                    mma_bf16(acc[mi][ni], afr[mi][0], afr[mi][1], afr[mi][2], afr[mi][3], b0, b1);
            }
        }
        __syncthreads();
    }

    // ---- epilogue (fp32 + bias) ----
#pragma unroll
    for (int mi = 0; mi < 4; mi++) {
#pragma unroll
        for (int ni = 0; ni < 4; ni++) {
            int r0 = bm + mBase + mi * 16 + grp;
            int c0 = bn + nBase + ni * 8 + tig * 2;
            float bv0 = (bias && c0     < N) ? bias[c0]     : 0.f;
            float bv1 = (bias && c0 + 1 < N) ? bias[c0 + 1] : 0.f;
            if (r0 < M) {
                if (c0     < N) C[(long)r0 * N + c0]     = acc[mi][ni][0] + bv0;
                if (c0 + 1 < N) C[(long)r0 * N + c0 + 1] = acc[mi][ni][1] + bv1;
            }
            int r1 = r0 + 8;
            if (r1 < M) {
                if (c0     < N) C[(long)r1 * N + c0]     = acc[mi][ni][2] + bv0;
                if (c0 + 1 < N) C[(long)r1 * N + c0 + 1] = acc[mi][ni][3] + bv1;
            }
        }
    }
}

// =====================================================================
// Tensor-core LSTM recurrence, cluster of 8 CTAs, 256 threads (8 warps).
// Rank r owns 128 z-columns: j=g*32+u -> global col g*256 + r*32 + u.
// Warp w owns n-slice [w*16, w*16+16); B=U fragments resident in registers
// (64 regs). h kept in SMEM as bf16 [2][16][256+pad] (rows >= BSUB zero).
// z accumulated fp32 in-register over full k=256 (no reduction).
// One cluster barrier per step; h pushed to all ranks via st.shared::cluster.
// =====================================================================
template<int BSUB, bool WRITE_HS>
__device__ __forceinline__ void lstm_body_tc(
    const float* __restrict__ Z, const float* __restrict__ U,
    void* __restrict__ OUT, int sbase, int dir)
{
    __shared__ __align__(16) unsigned short hb[2][16][264]; // 132 u32 words/row
    __shared__ __align__(16) float zbuf[8][132];

    const int tid = threadIdx.x;
    const int warp = tid >> 5, lane = tid & 31;
    const int tig = lane & 3, grp = lane >> 2;
    const unsigned r = ctarank();
    const int nbase = warp * 16;

    // ---- load recurrent weight fragments (resident) ----
    uint BF[16][2][2];
#pragma unroll
    for (int kt = 0; kt < 16; kt++) {
#pragma unroll
        for (int nt = 0; nt < 2; nt++) {
            int n = nbase + nt * 8 + grp;
            int c = ((n >> 5) << 8) + (int)r * 32 + (n & 31);
            int k0 = kt * 16 + tig * 2;
            BF[kt][nt][0] = pack2bf(U[(long)(k0    ) * 1024 + c], U[(long)(k0 + 1) * 1024 + c]);
            BF[kt][nt][1] = pack2bf(U[(long)(k0 + 8) * 1024 + c], U[(long)(k0 + 9) * 1024 + c]);
        }
    }
    // zero h (both buffers incl. pad rows)
    uint* hbw = (uint*)&hb[0][0][0];
    for (int i = tid; i < 2 * 16 * 132; i += 256) hbw[i] = 0;
    __syncthreads();
    cluster_sync_all();   // all ranks zeroed before any remote push

    const bool is_cell = tid < BSUB * 16;
    const int cs = tid >> 4;            // sample
    const int up = tid & 15;            // unit pair
    const int u2 = up * 2;
    float cst0 = 0.f, cst1 = 0.f;
    const unsigned hb_s = (unsigned)__cvta_generic_to_shared(&hb[0][0][0]);
    const int rowA = grp * 132, rowB = (grp + 8) * 132;

    int cur = 0;
    for (int step = 0; step < Tn; ++step) {
        const int t = dir ? (Tn - 1 - step) : step;
        const int nxt = cur ^ 1;

        // prefetch z_in (hides under matvec)
        float2 zin[4];
        if (is_cell) {
            const float* zr = Z + ((long)(sbase + cs) * Tn + t) * 1024 + (int)r * 32 + u2;
#pragma unroll
            for (int g = 0; g < 4; g++) zin[g] = *(const float2*)(zr + (g << 8));
        }

        // ---- z = h @ U (tensor cores, full k in-register) ----
        float acc0[4] = {0.f, 0.f, 0.f, 0.f};
        float acc1[4] = {0.f, 0.f, 0.f, 0.f};
        const uint* hp = (const uint*)&hb[cur][0][0];
#pragma unroll
        for (int kt = 0; kt < 16; kt++) {
            int w0 = kt * 8 + tig;
            uint a0 = hp[rowA + w0];
            uint a1 = hp[rowB + w0];
            uint a2 = hp[rowA + w0 + 4];
            uint a3 = hp[rowB + w0 + 4];
            mma_bf16(acc0, a0, a1, a2, a3, BF[kt][0][0], BF[kt][0][1]);
            mma_bf16(acc1, a0, a1, a2, a3, BF[kt][1][0], BF[kt][1][1]);
        }
        // valid rows are 0..7 (c0,c1 of the m16 tile)
        *(float2*)&zbuf[grp][nbase + tig * 2]     = make_float2(acc0[0], acc0[1]);
        *(float2*)&zbuf[grp][nbase + 8 + tig * 2] = make_float2(acc1[0], acc1[1]);
        __syncthreads();

        // ---- cell update (2 units per thread) ----
        if (is_cell) {
            float zi0 = zbuf[cs][     u2] + zin[0].x, zi1 = zbuf[cs][     u2 + 1] + zin[0].y;
            float zf0 = zbuf[cs][32 + u2] + zin[1].x, zf1 = zbuf[cs][32 + u2 + 1] + zin[1].y;
            float zg0 = zbuf[cs][64 + u2] + zin[2].x, zg1 = zbuf[cs][64 + u2 + 1] + zin[2].y;
            float zo0 = zbuf[cs][96 + u2] + zin[3].x, zo1 = zbuf[cs][96 + u2 + 1] + zin[3].y;
            cst0 = sigmoidf_(zf0) * cst0 + sigmoidf_(zi0) * fmaxf(zg0, 0.f);
            cst1 = sigmoidf_(zf1) * cst1 + sigmoidf_(zi1) * fmaxf(zg1, 0.f);
            float h0 = sigmoidf_(zo0) * fmaxf(cst0, 0.f);
            float h1 = sigmoidf_(zo1) * fmaxf(cst1, 0.f);
            uint hv = pack2bf(h0, h1);
            unsigned loff = hb_s + (unsigned)((nxt * 16 + cs) * 132 + (int)r * 16 + up) * 4u;
#pragma unroll
            for (unsigned tr = 0; tr < 8; tr++) st_cluster_u32(loff, tr, hv);

            if (WRITE_HS) {
                *(uint*)((__nv_bfloat16*)OUT +
                         ((long)(sbase + cs) * Tn + t) * 512 + dir * 256 + (int)r * 32 + u2) = hv;
            } else if (step == Tn - 1) {
                float* o = (float*)OUT + (sbase + cs) * 256 + (int)r * 32 + u2;
                o[0] = h0; o[1] = h1;
            }
        }
        cluster_sync_all();
        cur = nxt;
    }
}

__global__ void __cluster_dims__(8, 1, 1) __launch_bounds__(256, 1)
lstm1_kernel(const float* __restrict__ Zf, const float* __restrict__ Zb,
             const float* __restrict__ Uf, const float* __restrict__ Ub,
             __nv_bfloat16* __restrict__ HS)
{
    int cid = blockIdx.x >> 3;
    int dir = cid >> 3;
    int cl  = cid & 7;
    lstm_body_tc<8, true>(dir ? Zb : Zf, dir ? Ub : Uf, HS, cl * 8, dir);
}

__global__ void __cluster_dims__(8, 1, 1) __launch_bounds__(256, 1)
lstm2_kernel(const float* __restrict__ Z, const float* __restrict__ U,
             float* __restrict__ HL)
{
    int cid = blockIdx.x >> 3;
    lstm_body_tc<4, false>(Z, U, HL, cid * 4, 0);
}

// =====================================================================
// Dense head + softmax
// =====================================================================
__global__ __launch_bounds__(256) void dense3_kernel(
    const float* __restrict__ HL, const float* __restrict__ W3,
    const float* __restrict__ b3, float* __restrict__ D3)
{
    __shared__ float h[256];
    int s = blockIdx.x;
    h[threadIdx.x] = HL[s * 256 + threadIdx.x];
    __syncthreads();
    for (int j = threadIdx.x; j < U3n; j += 256) {
        float acc = b3[j];
#pragma unroll 8
        for (int k = 0; k < 256; k++) acc = fmaf(h[k], W3[k * U3n + j], acc);
        D3[s * U3n + j] = fmaxf(acc, 0.f);
    }
}

__global__ __launch_bounds__(256) void softmax_kernel(float* __restrict__ X)
{
    __shared__ float red[256];
    float* x = X + (long)blockIdx.x * U4n;
    int tid = threadIdx.x;

    float m = -1e30f;
    for (int j = tid; j < U4n; j += 256) m = fmaxf(m, x[j]);
    red[tid] = m; __syncthreads();
    for (int s = 128; s > 0; s >>= 1) {
        if (tid < s) red[tid] = fmaxf(red[tid], red[tid + s]);
        __syncthreads();
    }
    m = red[0]; __syncthreads();

    float sum = 0.f;
    for (int j = tid; j < U4n; j += 256) {
        float e = __expf(x[j] - m);
        x[j] = e;
        sum += e;
    }
    red[tid] = sum; __syncthreads();
    for (int s = 128; s > 0; s >>= 1) {
        if (tid < s) red[tid] += red[tid + s];
        __syncthreads();
    }
    float inv = 1.f / red[0];
    __syncthreads();
    for (int j = tid; j < U4n; j += 256) x[j] *= inv;
}

// =====================================================================
// launcher
// =====================================================================
extern "C" void kernel_launch(void* const* d_in, const int* in_sizes, int n_in,
                              void* d_out, int out_size)
{
    const int*   tokens = (const int*)  d_in[0];
    const float* emb    = (const float*)d_in[1];
    const float* W1f    = (const float*)d_in[2];
    const float* U1f    = (const float*)d_in[3];
    const float* b1f    = (const float*)d_in[4];
    const float* W1b    = (const float*)d_in[5];
    const float* U1b    = (const float*)d_in[6];
    const float* b1b    = (const float*)d_in[7];
    const float* W2     = (const float*)d_in[8];
    const float* U2m    = (const float*)d_in[9];
    const float* b2     = (const float*)d_in[10];
    const float* W3     = (const float*)d_in[11];
    const float* b3     = (const float*)d_in[12];
    const float* W4     = (const float*)d_in[13];
    const float* b4     = (const float*)d_in[14];
    float* out = (float*)d_out;

    float *Z1f, *Z1b, *Z2, *HL, *D3;
    __nv_bfloat16* HS;
    cudaGetSymbolAddress((void**)&Z1f, g_Z1f);
    cudaGetSymbolAddress((void**)&Z1b, g_Z1b);
    cudaGetSymbolAddress((void**)&HS,  g_HS);
    cudaGetSymbolAddress((void**)&Z2,  g_Z2);
    cudaGetSymbolAddress((void**)&HL,  g_HL);
    cudaGetSymbolAddress((void**)&D3,  g_D3);

    // 1) embedding gather + LSTM1 input projections (bias folded)
    {
        dim3 grid(8, 128);
        gemm_bf16<<<grid, 256>>>(emb, 0, W1f, b1f, Z1f, tokens, ROWS, 4 * H1, En, En);
        gemm_bf16<<<grid, 256>>>(emb, 0, W1b, b1b, Z1b, tokens, ROWS, 4 * H1, En, En);
    }
    // 2) BiLSTM layer 1 (both directions, one launch)
    lstm1_kernel<<<128, 256>>>(Z1f, Z1b, U1f, U1b, HS);
    // 3) LSTM2 input projection (A = HS, bf16)
    {
        dim3 grid(8, 128);
        gemm_bf16<<<grid, 256>>>(HS, 1, W2, b2, Z2, nullptr, ROWS, 4 * H2, 2 * H1, 2 * H1);
    }
    // 4) LSTM2 (h_last only)
    lstm2_kernel<<<128, 256>>>(Z2, U2m, HL);
    // 5) dense relu
    dense3_kernel<<<Bn, 256>>>(HL, W3, b3, D3);
    // 6) logits GEMM into d_out
    {
        dim3 grid((U4n + 127) / 128, 1);
        gemm_bf16<<<grid, 256>>>(D3, 0, W4, b4, out, nullptr, Bn, U4n, U3n, U3n);
    }
    // 7) softmax in place
    softmax_kernel<<<Bn, 256>>>(out);
}

// round 4
// speedup vs baseline: 2.6447x; 1.2018x over previous
#include <cuda_runtime.h>
#include <cuda_bf16.h>
#include <cstdint>

typedef unsigned int uint;

// ---------------- problem constants ----------------
#define Bn   64
#define Tn   256
#define En   128
#define H1   256
#define H2   256
#define U3n  512
#define U4n  5000
#define ROWS (Bn*Tn)      // 16384

// ---------------- scratch ----------------
__device__ float g_Z1f[ROWS * 1024];
__device__ float g_Z1b[ROWS * 1024];
__device__ __nv_bfloat16 g_HS[ROWS * 512];
__device__ float g_Z2 [ROWS * 1024];
__device__ float g_HL [Bn * H2];
__device__ __nv_bfloat16 g_D3bf[Bn * U3n];
__device__ __nv_bfloat16 g_emb_bf[50000 * En];
__device__ __nv_bfloat16 g_W1f_bf[En * 1024];
__device__ __nv_bfloat16 g_W1b_bf[En * 1024];
__device__ __nv_bfloat16 g_W2_bf [512 * 1024];
__device__ __nv_bfloat16 g_W4_bf [512 * U4n];

// ---------------- helpers ----------------
__device__ __forceinline__ unsigned ctarank() {
    unsigned r; asm("mov.u32 %0, %%cluster_ctarank;" : "=r"(r)); return r;
}
__device__ __forceinline__ void cluster_sync_all() {
    asm volatile("barrier.cluster.arrive.aligned;\n\tbarrier.cluster.wait.aligned;" ::: "memory");
}
__device__ __forceinline__ void st_cluster_u32(unsigned local_addr, unsigned rank, uint v) {
    unsigned ra;
    asm volatile("mapa.shared::cluster.u32 %0, %1, %2;" : "=r"(ra) : "r"(local_addr), "r"(rank));
    asm volatile("st.shared::cluster.b32 [%0], %1;" :: "r"(ra), "r"(v) : "memory");
}
__device__ __forceinline__ void mbar_arrive_remote(unsigned local_mbar, unsigned rank) {
    unsigned ra;
    asm volatile("mapa.shared::cluster.u32 %0, %1, %2;" : "=r"(ra) : "r"(local_mbar), "r"(rank));
    asm volatile("mbarrier.arrive.release.cluster.shared::cluster.b64 _, [%0];" :: "r"(ra) : "memory");
}
__device__ __forceinline__ void mbar_wait(unsigned addr, unsigned parity) {
    asm volatile(
        "{\n\t.reg .pred P;\n"
        "LW_%=:\n\t"
        "mbarrier.try_wait.parity.acquire.cluster.shared::cta.b64 P, [%0], %1;\n\t"
        "@P bra LD_%=;\n\t"
        "bra LW_%=;\n"
        "LD_%=:\n\t}"
        :: "r"(addr), "r"(parity) : "memory");
}
__device__ __forceinline__ uint pack2bf(float a, float b) {
    __nv_bfloat162 t = __floats2bfloat162_rn(a, b);
    return *(uint*)&t;
}
__device__ __forceinline__ void mma_bf16(float* d,
                                         uint a0, uint a1, uint a2, uint a3,
                                         uint b0, uint b1) {
    asm volatile("mma.sync.aligned.m16n8k16.row.col.f32.bf16.bf16.f32 "
                 "{%0,%1,%2,%3},{%4,%5,%6,%7},{%8,%9},{%0,%1,%2,%3};"
                 : "+f"(d[0]), "+f"(d[1]), "+f"(d[2]), "+f"(d[3])
                 : "r"(a0), "r"(a1), "r"(a2), "r"(a3), "r"(b0), "r"(b1));
}
__device__ __forceinline__ void ldsm_x4(uint& r0, uint& r1, uint& r2, uint& r3, unsigned a) {
    asm volatile("ldmatrix.sync.aligned.m8n8.x4.shared.b16 {%0,%1,%2,%3}, [%4];"
                 : "=r"(r0), "=r"(r1), "=r"(r2), "=r"(r3) : "r"(a));
}
__device__ __forceinline__ void ldsm_x4t(uint& r0, uint& r1, uint& r2, uint& r3, unsigned a) {
    asm volatile("ldmatrix.sync.aligned.m8n8.x4.trans.shared.b16 {%0,%1,%2,%3}, [%4];"
                 : "=r"(r0), "=r"(r1), "=r"(r2), "=r"(r3) : "r"(a));
}
__device__ __forceinline__ void cp_async16(unsigned saddr, const void* gaddr) {
    asm volatile("cp.async.cg.shared.global [%0], [%1], 16;" :: "r"(saddr), "l"(gaddr));
}
__device__ __forceinline__ float sigmoidf_(float z) {
    return 1.0f / (1.0f + __expf(-z));
}

// =====================================================================
// f32 -> bf16 conversion (vectorized, grid-stride). n % 4 == 0.
// =====================================================================
__global__ __launch_bounds__(256) void f2bf_kernel(
    const float* __restrict__ s, __nv_bfloat16* __restrict__ d, int n4)
{
    int i = blockIdx.x * blockDim.x + threadIdx.x;
    int stride = gridDim.x * blockDim.x;
    for (; i < n4; i += stride) {
        float4 v = ((const float4*)s)[i];
        uint2 w;
        w.x = pack2bf(v.x, v.y);
        w.y = pack2bf(v.z, v.w);
        ((uint2*)d)[i] = w;
    }
}

// =====================================================================
// bf16 GEMM v2:  C[M,N] = gather(A)[M,K] @ B[K,N] + bias   (fp32 out)
// A, B bf16. BM=128, BN=128, BK=64, 256 threads, warp tile 64x32.
// cp.async double-buffered staging; ldmatrix fragment loads.
// K % 64 == 0, N % 8 == 0, M arbitrary.
// SMEM: A stages 2x128x144B @ 0, B stages 2x64x272B @ 36864, toks @ 71680.
// =====================================================================
__global__ __launch_bounds__(256) void gemm_bf16_v2(
    const __nv_bfloat16* __restrict__ A, const __nv_bfloat16* __restrict__ B,
    const float* __restrict__ bias, float* __restrict__ C,
    const int* __restrict__ gather, int M, int N, int K, int lda)
{
    extern __shared__ char dynsm[];
    const unsigned sbase = (unsigned)__cvta_generic_to_shared(dynsm);
    int* toks = (int*)(dynsm + 71680);

    const int bm = blockIdx.y * 128;
    const int bn = blockIdx.x * 128;
    const int tid = threadIdx.x;
    const int warp = tid >> 5, lane = tid & 31;
    const int wm = warp >> 2, wn = warp & 3;
    const int mBase = wm * 64, nBase = wn * 32;
    const int grp = lane >> 2, tig = lane & 3;

    if (gather && tid < 128) toks[tid] = (bm + tid < M) ? gather[bm + tid] : 0;
    __syncthreads();

    auto stage = [&](int kb, int st) {
        // A tile: 128 rows x 64 bf16 (128B/row), row stride 144B
#pragma unroll
        for (int i = 0; i < 4; i++) {
            int idx = tid + i * 256;
            int row = idx >> 3, ch = idx & 7;
            unsigned off = (unsigned)(st * 18432 + row * 144 + ch * 16);
            if (bm + row < M) {
                long r = gather ? (long)toks[row] : (long)(bm + row);
                cp_async16(sbase + off, A + r * (long)lda + kb * 64 + ch * 8);
            } else {
                *(uint4*)(dynsm + off) = make_uint4(0, 0, 0, 0);
            }
        }
        // B tile: 64 rows x 128 bf16 (256B/row), row stride 272B
#pragma unroll
        for (int i = 0; i < 4; i++) {
            int idx = tid + i * 256;
            int k = idx >> 4, ch = idx & 15;
            int gc = bn + ch * 8;
            unsigned off = (unsigned)(36864 + st * 17408 + k * 272 + ch * 16);
            if (gc < N) {
                cp_async16(sbase + off, B + (long)(kb * 64 + k) * N + gc);
            } else {
                *(uint4*)(dynsm + off) = make_uint4(0, 0, 0, 0);
            }
        }
        asm volatile("cp.async.commit_group;");
    };

    float acc[4][4][4];
#pragma unroll
    for (int a = 0; a < 4; a++)
#pragma unroll
        for (int b = 0; b < 4; b++)
#pragma unroll
            for (int c = 0; c < 4; c++) acc[a][b][c] = 0.f;

    const int nk = K >> 6;
    stage(0, 0);

    for (int kb = 0; kb < nk; kb++) {
        int st = kb & 1;
        if (kb + 1 < nk) {
            stage(kb + 1, st ^ 1);
            asm volatile("cp.async.wait_group 1;");
        } else {
            asm volatile("cp.async.wait_group 0;");
        }
        __syncthreads();

        // fragment base addresses (ldmatrix lane addressing)
        unsigned aRow = sbase + (unsigned)(st * 18432)
                      + (unsigned)((mBase + (lane & 15)) * 144)
                      + (unsigned)((lane >> 4) << 4);
        unsigned bCol = sbase + 36864u + (unsigned)(st * 17408)
                      + (unsigned)((lane & 15) * 272)
                      + (unsigned)(nBase * 2 + ((lane >> 4) << 4));

#pragma unroll
        for (int kt = 0; kt < 4; kt++) {
            uint afr[4][4];
#pragma unroll
            for (int mi = 0; mi < 4; mi++)
                ldsm_x4(afr[mi][0], afr[mi][1], afr[mi][2], afr[mi][3],
                        aRow + (unsigned)(mi * 16 * 144 + kt * 32));
            uint bfr[2][4];
#pragma unroll
            for (int nh = 0; nh < 2; nh++)
                ldsm_x4t(bfr[nh][0], bfr[nh][1], bfr[nh][2], bfr[nh][3],
                         bCol + (unsigned)(kt * 16 * 272 + nh * 32));
#pragma unroll
            for (int nh = 0; nh < 2; nh++)
#pragma unroll
                for (int hf = 0; hf < 2; hf++) {
                    int ni = nh * 2 + hf;
                    uint b0 = bfr[nh][hf * 2], b1 = bfr[nh][hf * 2 + 1];
#pragma unroll
                    for (int mi = 0; mi < 4; mi++)
                        mma_bf16(acc[mi][ni], afr[mi][0], afr[mi][1], afr[mi][2], afr[mi][3], b0, b1);
                }
        }
        __syncthreads();
    }

    // ---- epilogue ----
#pragma unroll
    for (int mi = 0; mi < 4; mi++) {
#pragma unroll
        for (int ni = 0; ni < 4; ni++) {
            int r0 = bm + mBase + mi * 16 + grp;
            int c0 = bn + nBase + ni * 8 + tig * 2;
            float bv0 = (bias && c0     < N) ? bias[c0]     : 0.f;
            float bv1 = (bias && c0 + 1 < N) ? bias[c0 + 1] : 0.f;
            if (r0 < M) {
                if (c0     < N) C[(long)r0 * N + c0]     = acc[mi][ni][0] + bv0;
                if (c0 + 1 < N) C[(long)r0 * N + c0 + 1] = acc[mi][ni][1] + bv1;
            }
            int r1 = r0 + 8;
            if (r1 < M) {
                if (c0     < N) C[(long)r1 * N + c0]     = acc[mi][ni][2] + bv0;
                if (c0 + 1 < N) C[(long)r1 * N + c0 + 1] = acc[mi][ni][3] + bv1;
            }
        }
    }
}

// =====================================================================
// Tensor-core LSTM recurrence, cluster of 8 CTAs, 256 threads (8 warps).
// Rank r owns 128 z-cols (j=g*32+u -> global g*256+r*32+u); warp w owns
// n-slice [w*16, w*16+16); U frags resident in registers (64 regs).
// h double-buffered bf16 in SMEM; per-step sync = per-CTA mbarrier with
// 8 remote release-arrives (one per cluster CTA) instead of barrier.cluster.
// =====================================================================
template<int BSUB, bool WRITE_HS>
__device__ __forceinline__ void lstm_body_tc(
    const float* __restrict__ Z, const float* __restrict__ U,
    void* __restrict__ OUT, int sbase, int dir)
{
    constexpr int CELLN = BSUB * 16;
    __shared__ __align__(16) unsigned short hb[2][16][264];  // 528B rows (33x16B)
    __shared__ __align__(16) float zbuf[8][132];
    __shared__ __align__(8) unsigned long long mbar;

    const int tid = threadIdx.x;
    const int warp = tid >> 5, lane = tid & 31;
    const int tig = lane & 3, grp = lane >> 2;
    const unsigned r = ctarank();
    const int nbase = warp * 16;

    // ---- resident recurrent-weight fragments ----
    uint BF[16][2][2];
#pragma unroll
    for (int kt = 0; kt < 16; kt++) {
#pragma unroll
        for (int nt = 0; nt < 2; nt++) {
            int n = nbase + nt * 8 + grp;
            int c = ((n >> 5) << 8) + (int)r * 32 + (n & 31);
            int k0 = kt * 16 + tig * 2;
            BF[kt][nt][0] = pack2bf(U[(long)(k0    ) * 1024 + c], U[(long)(k0 + 1) * 1024 + c]);
            BF[kt][nt][1] = pack2bf(U[(long)(k0 + 8) * 1024 + c], U[(long)(k0 + 9) * 1024 + c]);
        }
    }
    // zero both h buffers
    uint* hbw = (uint*)&hb[0][0][0];
    for (int i = tid; i < 2 * 16 * 132; i += 256) hbw[i] = 0;
    const unsigned mbar_s = (unsigned)__cvta_generic_to_shared(&mbar);
    if (tid == 0)
        asm volatile("mbarrier.init.shared.b64 [%0], 8;" :: "r"(mbar_s) : "memory");
    __syncthreads();
    cluster_sync_all();   // mbarriers + zeroed buffers visible cluster-wide

    const bool is_cell = tid < CELLN;
    const int cs = tid >> 4;
    const int up = tid & 15;
    const int u2 = up * 2;
    float cst0 = 0.f, cst1 = 0.f;
    const unsigned hb_s = (unsigned)__cvta_generic_to_shared(&hb[0][0][0]);

    for (int step = 0; step < Tn; ++step) {
        const int cur = step & 1, nxt = cur ^ 1;
        const int t = dir ? (Tn - 1 - step) : step;

        // z prefetch (issued before the wait to overlap DRAM latency)
        float2 zin[4];
        if (is_cell) {
            const float* zr = Z + ((long)(sbase + cs) * Tn + t) * 1024 + (int)r * 32 + u2;
#pragma unroll
            for (int g = 0; g < 4; g++) zin[g] = *(const float2*)(zr + (g << 8));
        }
        if (step > 0) mbar_wait(mbar_s, (unsigned)((step - 1) & 1));

        // ---- z = h @ U : 4 independent 8-deep HMMA chains ----
        float a0c[4] = {0,0,0,0}, a1c[4] = {0,0,0,0};
        float a0d[4] = {0,0,0,0}, a1d[4] = {0,0,0,0};
        unsigned hrow = hb_s + (unsigned)((cur * 16 + (lane & 15)) * 528)
                             + (unsigned)((lane >> 4) << 4);
#pragma unroll
        for (int kt = 0; kt < 16; kt += 2) {
            uint x0, x1, x2, x3;
            ldsm_x4(x0, x1, x2, x3, hrow + (unsigned)(kt * 32));
            mma_bf16(a0c, x0, x1, x2, x3, BF[kt][0][0], BF[kt][0][1]);
            mma_bf16(a1c, x0, x1, x2, x3, BF[kt][1][0], BF[kt][1][1]);
            uint y0, y1, y2, y3;
            ldsm_x4(y0, y1, y2, y3, hrow + (unsigned)(kt * 32 + 32));
            mma_bf16(a0d, y0, y1, y2, y3, BF[kt + 1][0][0], BF[kt + 1][0][1]);
            mma_bf16(a1d, y0, y1, y2, y3, BF[kt + 1][1][0], BF[kt + 1][1][1]);
        }
        *(float2*)&zbuf[grp][nbase + tig * 2] =
            make_float2(a0c[0] + a0d[0], a0c[1] + a0d[1]);
        *(float2*)&zbuf[grp][nbase + 8 + tig * 2] =
            make_float2(a1c[0] + a1d[0], a1c[1] + a1d[1]);
        __syncthreads();

        // ---- cell update (2 units per thread) ----
        if (is_cell) {
            float zi0 = zbuf[cs][     u2] + zin[0].x, zi1 = zbuf[cs][     u2 + 1] + zin[0].y;
            float zf0 = zbuf[cs][32 + u2] + zin[1].x, zf1 = zbuf[cs][32 + u2 + 1] + zin[1].y;
            float zg0 = zbuf[cs][64 + u2] + zin[2].x, zg1 = zbuf[cs][64 + u2 + 1] + zin[2].y;
            float zo0 = zbuf[cs][96 + u2] + zin[3].x, zo1 = zbuf[cs][96 + u2 + 1] + zin[3].y;
            cst0 = sigmoidf_(zf0) * cst0 + sigmoidf_(zi0) * fmaxf(zg0, 0.f);
            cst1 = sigmoidf_(zf1) * cst1 + sigmoidf_(zi1) * fmaxf(zg1, 0.f);
            float h0 = sigmoidf_(zo0) * fmaxf(cst0, 0.f);
            float h1 = sigmoidf_(zo1) * fmaxf(cst1, 0.f);
            uint hv = pack2bf(h0, h1);

            if (step < Tn - 1) {
                unsigned loff = hb_s + (unsigned)((nxt * 16 + cs) * 132 + (int)r * 16 + up) * 4u;
#pragma unroll
                for (unsigned tr = 0; tr < 8; tr++) st_cluster_u32(loff, tr, hv);
            }
            if (WRITE_HS) {
                *(uint*)((__nv_bfloat16*)OUT +
                         ((long)(sbase + cs) * Tn + t) * 512 + dir * 256 + (int)r * 32 + u2) = hv;
            } else if (step == Tn - 1) {
                float* o = (float*)OUT + (sbase + cs) * 256 + (int)r * 32 + u2;
                o[0] = h0; o[1] = h1;
            }
            if (step < Tn - 1) {
                asm volatile("bar.sync 1, %0;" :: "r"(CELLN) : "memory");
                if (tid < 8) mbar_arrive_remote(mbar_s, (unsigned)tid);
            }
        }
    }
    cluster_sync_all();   // no CTA exits while cluster peers may touch its SMEM
}

__global__ void __cluster_dims__(8, 1, 1) __launch_bounds__(256, 1)
lstm1_kernel(const float* __restrict__ Zf, const float* __restrict__ Zb,
             const float* __restrict__ Uf, const float* __restrict__ Ub,
             __nv_bfloat16* __restrict__ HS)
{
    int cid = blockIdx.x >> 3;
    int dir = cid >> 3;
    int cl  = cid & 7;
    lstm_body_tc<8, true>(dir ? Zb : Zf, dir ? Ub : Uf, HS, cl * 8, dir);
}

__global__ void __cluster_dims__(8, 1, 1) __launch_bounds__(256, 1)
lstm2_kernel(const float* __restrict__ Z, const float* __restrict__ U,
             float* __restrict__ HL)
{
    int cid = blockIdx.x >> 3;
    lstm_body_tc<4, false>(Z, U, HL, cid * 4, 0);
}

// =====================================================================
// Dense head + softmax
// =====================================================================
__global__ __launch_bounds__(256) void dense3_kernel(
    const float* __restrict__ HL, const float* __restrict__ W3,
    const float* __restrict__ b3, __nv_bfloat16* __restrict__ D3bf)
{
    __shared__ float h[256];
    int s = blockIdx.x;
    h[threadIdx.x] = HL[s * 256 + threadIdx.x];
    __syncthreads();
    for (int j = threadIdx.x; j < U3n; j += 256) {
        float acc = b3[j];
#pragma unroll 8
        for (int k = 0; k < 256; k++) acc = fmaf(h[k], W3[k * U3n + j], acc);
        D3bf[s * U3n + j] = __float2bfloat16_rn(fmaxf(acc, 0.f));
    }
}

__global__ __launch_bounds__(256) void softmax_kernel(float* __restrict__ X)
{
    __shared__ float red[256];
    float* x = X + (long)blockIdx.x * U4n;
    int tid = threadIdx.x;

    float m = -1e30f;
    for (int j = tid; j < U4n; j += 256) m = fmaxf(m, x[j]);
    red[tid] = m; __syncthreads();
    for (int s = 128; s > 0; s >>= 1) {
        if (tid < s) red[tid] = fmaxf(red[tid], red[tid + s]);
        __syncthreads();
    }
    m = red[0]; __syncthreads();

    float sum = 0.f;
    for (int j = tid; j < U4n; j += 256) {
        float e = __expf(x[j] - m);
        x[j] = e;
        sum += e;
    }
    red[tid] = sum; __syncthreads();
    for (int s = 128; s > 0; s >>= 1) {
        if (tid < s) red[tid] += red[tid + s];
        __syncthreads();
    }
    float inv = 1.f / red[0];
    __syncthreads();
    for (int j = tid; j < U4n; j += 256) x[j] *= inv;
}

// =====================================================================
// launcher
// =====================================================================
extern "C" void kernel_launch(void* const* d_in, const int* in_sizes, int n_in,
                              void* d_out, int out_size)
{
    const int*   tokens = (const int*)  d_in[0];
    const float* emb    = (const float*)d_in[1];
    const float* W1f    = (const float*)d_in[2];
    const float* U1f    = (const float*)d_in[3];
    const float* b1f    = (const float*)d_in[4];
    const float* W1b    = (const float*)d_in[5];
    const float* U1b    = (const float*)d_in[6];
    const float* b1b    = (const float*)d_in[7];
    const float* W2     = (const float*)d_in[8];
    const float* U2m    = (const float*)d_in[9];
    const float* b2     = (const float*)d_in[10];
    const float* W3     = (const float*)d_in[11];
    const float* b3     = (const float*)d_in[12];
    const float* W4     = (const float*)d_in[13];
    const float* b4     = (const float*)d_in[14];
    float* out = (float*)d_out;

    float *Z1f, *Z1b, *Z2, *HL;
    __nv_bfloat16 *HS, *D3bf, *emb_bf, *W1f_bf, *W1b_bf, *W2_bf, *W4_bf;
    cudaGetSymbolAddress((void**)&Z1f,    g_Z1f);
    cudaGetSymbolAddress((void**)&Z1b,    g_Z1b);
    cudaGetSymbolAddress((void**)&HS,     g_HS);
    cudaGetSymbolAddress((void**)&Z2,     g_Z2);
    cudaGetSymbolAddress((void**)&HL,     g_HL);
    cudaGetSymbolAddress((void**)&D3bf,   g_D3bf);
    cudaGetSymbolAddress((void**)&emb_bf, g_emb_bf);
    cudaGetSymbolAddress((void**)&W1f_bf, g_W1f_bf);
    cudaGetSymbolAddress((void**)&W1b_bf, g_W1b_bf);
    cudaGetSymbolAddress((void**)&W2_bf,  g_W2_bf);
    cudaGetSymbolAddress((void**)&W4_bf,  g_W4_bf);

    const int GEMM_SMEM = 72192;
    cudaFuncSetAttribute((const void*)gemm_bf16_v2,
                         cudaFuncAttributeMaxDynamicSharedMemorySize, GEMM_SMEM);

    // 0) one-time-per-call f32 -> bf16 conversions
    f2bf_kernel<<<2048, 256>>>(emb, emb_bf, 50000 * En / 4);
    f2bf_kernel<<<128,  256>>>(W1f, W1f_bf, En * 1024 / 4);
    f2bf_kernel<<<128,  256>>>(W1b, W1b_bf, En * 1024 / 4);
    f2bf_kernel<<<512,  256>>>(W2,  W2_bf,  512 * 1024 / 4);
    f2bf_kernel<<<1024, 256>>>(W4,  W4_bf,  512 * U4n / 4);

    // 1) embedding gather + LSTM1 input projections
    {
        dim3 grid(8, 128);
        gemm_bf16_v2<<<grid, 256, GEMM_SMEM>>>(emb_bf, W1f_bf, b1f, Z1f, tokens,
                                               ROWS, 1024, En, En);
        gemm_bf16_v2<<<grid, 256, GEMM_SMEM>>>(emb_bf, W1b_bf, b1b, Z1b, tokens,
                                               ROWS, 1024, En, En);
    }
    // 2) BiLSTM layer 1 (both directions, one launch)
    lstm1_kernel<<<128, 256>>>(Z1f, Z1b, U1f, U1b, HS);
    // 3) LSTM2 input projection
    {
        dim3 grid(8, 128);
        gemm_bf16_v2<<<grid, 256, GEMM_SMEM>>>(HS, W2_bf, b2, Z2, nullptr,
                                               ROWS, 1024, 512, 512);
    }
    // 4) LSTM2 (h_last only)
    lstm2_kernel<<<128, 256>>>(Z2, U2m, HL);
    // 5) dense relu -> bf16
    dense3_kernel<<<Bn, 256>>>(HL, W3, b3, D3bf);
    // 6) logits GEMM into d_out
    {
        dim3 grid((U4n + 127) / 128, 1);
        gemm_bf16_v2<<<grid, 256, GEMM_SMEM>>>(D3bf, W4_bf, b4, out, nullptr,
                                               Bn, U4n, U3n, U3n);
    }
    // 7) softmax in place
    softmax_kernel<<<Bn, 256>>>(out);
}

// round 5
// speedup vs baseline: 2.6567x; 1.0045x over previous
#include <cuda_runtime.h>
#include <cuda_bf16.h>
#include <cstdint>

typedef unsigned int uint;

// ---------------- problem constants ----------------
#define Bn   64
#define Tn   256
#define En   128
#define H1   256
#define H2   256
#define U3n  512
#define U4n  5000
#define ROWS (Bn*Tn)      // 16384

// ---------------- scratch ----------------
__device__ float g_Z1cat[ROWS * 2048];            // fw cols 0..1023, bw 1024..2047
__device__ float g_Z2 [ROWS * 1024];
__device__ __nv_bfloat16 g_HS[ROWS * 512];
__device__ float g_HL [Bn * H2];
__device__ __nv_bfloat16 g_D3bf[Bn * U3n];
__device__ __nv_bfloat16 g_Xbf[ROWS * En];        // gathered+converted embeddings
__device__ __nv_bfloat16 g_W1cat[En * 2048];
__device__ float g_bcat[2048];
__device__ __nv_bfloat16 g_W2_bf [512 * 1024];
__device__ __nv_bfloat16 g_W4_bf [512 * U4n];

// ---------------- helpers ----------------
__device__ __forceinline__ unsigned ctarank() {
    unsigned r; asm("mov.u32 %0, %%cluster_ctarank;" : "=r"(r)); return r;
}
__device__ __forceinline__ void cluster_sync_all() {
    asm volatile("barrier.cluster.arrive.aligned;\n\tbarrier.cluster.wait.aligned;" ::: "memory");
}
__device__ __forceinline__ void st_cluster_u32(unsigned local_addr, unsigned rank, uint v) {
    unsigned ra;
    asm volatile("mapa.shared::cluster.u32 %0, %1, %2;" : "=r"(ra) : "r"(local_addr), "r"(rank));
    asm volatile("st.shared::cluster.b32 [%0], %1;" :: "r"(ra), "r"(v) : "memory");
}
__device__ __forceinline__ void mbar_arrive_remote(unsigned local_mbar, unsigned rank) {
    unsigned ra;
    asm volatile("mapa.shared::cluster.u32 %0, %1, %2;" : "=r"(ra) : "r"(local_mbar), "r"(rank));
    asm volatile("mbarrier.arrive.release.cluster.shared::cluster.b64 _, [%0];" :: "r"(ra) : "memory");
}
__device__ __forceinline__ void mbar_wait(unsigned addr, unsigned parity) {
    asm volatile(
        "{\n\t.reg .pred P;\n"
        "LW_%=:\n\t"
        "mbarrier.try_wait.parity.acquire.cluster.shared::cta.b64 P, [%0], %1;\n\t"
        "@P bra LD_%=;\n\t"
        "bra LW_%=;\n"
        "LD_%=:\n\t}"
        :: "r"(addr), "r"(parity) : "memory");
}
__device__ __forceinline__ uint pack2bf(float a, float b) {
    __nv_bfloat162 t = __floats2bfloat162_rn(a, b);
    return *(uint*)&t;
}
__device__ __forceinline__ void mma_bf16(float* d,
                                         uint a0, uint a1, uint a2, uint a3,
                                         uint b0, uint b1) {
    asm volatile("mma.sync.aligned.m16n8k16.row.col.f32.bf16.bf16.f32 "
                 "{%0,%1,%2,%3},{%4,%5,%6,%7},{%8,%9},{%0,%1,%2,%3};"
                 : "+f"(d[0]), "+f"(d[1]), "+f"(d[2]), "+f"(d[3])
                 : "r"(a0), "r"(a1), "r"(a2), "r"(a3), "r"(b0), "r"(b1));
}
__device__ __forceinline__ void ldsm_x4(uint& r0, uint& r1, uint& r2, uint& r3, unsigned a) {
    asm volatile("ldmatrix.sync.aligned.m8n8.x4.shared.b16 {%0,%1,%2,%3}, [%4];"
                 : "=r"(r0), "=r"(r1), "=r"(r2), "=r"(r3) : "r"(a));
}
__device__ __forceinline__ void ldsm_x4t(uint& r0, uint& r1, uint& r2, uint& r3, unsigned a) {
    asm volatile("ldmatrix.sync.aligned.m8n8.x4.trans.shared.b16 {%0,%1,%2,%3}, [%4];"
                 : "=r"(r0), "=r"(r1), "=r"(r2), "=r"(r3) : "r"(a));
}
__device__ __forceinline__ void cp_async16(unsigned saddr, const void* gaddr) {
    asm volatile("cp.async.cg.shared.global [%0], [%1], 16;" :: "r"(saddr), "l"(gaddr));
}
__device__ __forceinline__ float sigmoidf_(float z) {
    return 1.0f / (1.0f + __expf(-z));
}

// =====================================================================
// Fused gather + f32->bf16: Xbf[i,:] = bf16(emb[tokens[i],:])
// grid 2048 x 256: one warp per row chunk; unit = one float4.
// =====================================================================
__global__ __launch_bounds__(256) void gatherconv_kernel(
    const float* __restrict__ emb, const int* __restrict__ tokens,
    __nv_bfloat16* __restrict__ Xbf)
{
    int u = blockIdx.x * 256 + threadIdx.x;        // 0 .. 16384*32-1
    int row = u >> 5;
    int c4 = (u & 31) << 2;
    long tok = tokens[row];
    float4 v = *(const float4*)&emb[tok * En + c4];
    uint2 w;
    w.x = pack2bf(v.x, v.y);
    w.y = pack2bf(v.z, v.w);
    *(uint2*)&Xbf[(long)row * En + c4] = w;
}

// =====================================================================
// Concat + convert LSTM1 weights: W1cat[k, 0:1024]=W1f[k], [1024:2048]=W1b[k]
// Also bcat. grid 256 x 256.
// =====================================================================
__global__ __launch_bounds__(256) void convcat_kernel(
    const float* __restrict__ W1f, const float* __restrict__ W1b,
    const float* __restrict__ b1f, const float* __restrict__ b1b,
    __nv_bfloat16* __restrict__ Wcat, float* __restrict__ bcat)
{
    int u = blockIdx.x * 256 + threadIdx.x;        // 0 .. 65535
    int row = u >> 9;
    int c4 = (u & 511) << 2;
    const float* src = (c4 < 1024) ? &W1f[row * 1024 + c4] : &W1b[row * 1024 + c4 - 1024];
    float4 v = *(const float4*)src;
    uint2 w;
    w.x = pack2bf(v.x, v.y);
    w.y = pack2bf(v.z, v.w);
    *(uint2*)&Wcat[(long)row * 2048 + c4] = w;
    if (blockIdx.x == 0) {
        for (int j = threadIdx.x; j < 1024; j += 256) {
            bcat[j] = b1f[j];
            bcat[1024 + j] = b1b[j];
        }
    }
}

// =====================================================================
// f32 -> bf16 conversion (vectorized, grid-stride). n % 4 == 0.
// =====================================================================
__global__ __launch_bounds__(256) void f2bf_kernel(
    const float* __restrict__ s, __nv_bfloat16* __restrict__ d, int n4)
{
    int i = blockIdx.x * blockDim.x + threadIdx.x;
    int stride = gridDim.x * blockDim.x;
    for (; i < n4; i += stride) {
        float4 v = ((const float4*)s)[i];
        uint2 w;
        w.x = pack2bf(v.x, v.y);
        w.y = pack2bf(v.z, v.w);
        ((uint2*)d)[i] = w;
    }
}

// =====================================================================
// bf16 GEMM v3:  C[M,N] = A[M,K] @ B[K,N] + bias   (fp32 out)
// A, B bf16. BM=128, BN=128, BK=64, 256 threads, warp tile 64x32.
// 3-stage cp.async pipeline; ldmatrix fragment loads.
// K % 64 == 0, N % 8 == 0, M arbitrary.
// SMEM: A stages 3x128x144B @ 0, B stages 3x64x272B @ 55296. Total 107520.
// =====================================================================
#define A_STG 18432
#define B_STG 17408
#define B_OFF 55296
#define GEMM_SMEM 107520

__global__ __launch_bounds__(256) void gemm_bf16_v3(
    const __nv_bfloat16* __restrict__ A, const __nv_bfloat16* __restrict__ B,
    const float* __restrict__ bias, float* __restrict__ C,
    int M, int N, int K, int lda)
{
    extern __shared__ char dynsm[];
    const unsigned sbase = (unsigned)__cvta_generic_to_shared(dynsm);

    const int bm = blockIdx.y * 128;
    const int bn = blockIdx.x * 128;
    const int tid = threadIdx.x;
    const int warp = tid >> 5, lane = tid & 31;
    const int wm = warp >> 2, wn = warp & 3;
    const int mBase = wm * 64, nBase = wn * 32;
    const int grp = lane >> 2, tig = lane & 3;

    auto stage = [&](int kb, int st) {
        // A tile: 128 rows x 64 bf16 (128B/row), row stride 144B
#pragma unroll
        for (int i = 0; i < 4; i++) {
            int idx = tid + i * 256;
            int row = idx >> 3, ch = idx & 7;
            unsigned off = (unsigned)(st * A_STG + row * 144 + ch * 16);
            if (bm + row < M) {
                cp_async16(sbase + off, A + (long)(bm + row) * lda + kb * 64 + ch * 8);
            } else {
                *(uint4*)(dynsm + off) = make_uint4(0, 0, 0, 0);
            }
        }
        // B tile: 64 rows x 128 bf16 (256B/row), row stride 272B
#pragma unroll
        for (int i = 0; i < 4; i++) {
            int idx = tid + i * 256;
            int k = idx >> 4, ch = idx & 15;
            int gc = bn + ch * 8;
            unsigned off = (unsigned)(B_OFF + st * B_STG + k * 272 + ch * 16);
            if (gc < N) {
                cp_async16(sbase + off, B + (long)(kb * 64 + k) * N + gc);
            } else {
                *(uint4*)(dynsm + off) = make_uint4(0, 0, 0, 0);
            }
        }
        asm volatile("cp.async.commit_group;");
    };

    float acc[4][4][4];
#pragma unroll
    for (int a = 0; a < 4; a++)
#pragma unroll
        for (int b = 0; b < 4; b++)
#pragma unroll
            for (int c = 0; c < 4; c++) acc[a][b][c] = 0.f;

    const int nk = K >> 6;
    stage(0, 0);
    if (nk > 1) stage(1, 1);

    for (int kb = 0; kb < nk; kb++) {
        int st = kb % 3;
        if (kb + 2 < nk) {
            stage(kb + 2, (kb + 2) % 3);
            asm volatile("cp.async.wait_group 2;");
        } else if (kb + 1 < nk) {
            asm volatile("cp.async.wait_group 1;");
        } else {
            asm volatile("cp.async.wait_group 0;");
        }
        __syncthreads();

        unsigned aRow = sbase + (unsigned)(st * A_STG)
                      + (unsigned)((mBase + (lane & 15)) * 144)
                      + (unsigned)((lane >> 4) << 4);
        unsigned bCol = sbase + (unsigned)(B_OFF + st * B_STG)
                      + (unsigned)((lane & 15) * 272)
                      + (unsigned)(nBase * 2 + ((lane >> 4) << 4));

#pragma unroll
        for (int kt = 0; kt < 4; kt++) {
            uint afr[4][4];
#pragma unroll
            for (int mi = 0; mi < 4; mi++)
                ldsm_x4(afr[mi][0], afr[mi][1], afr[mi][2], afr[mi][3],
                        aRow + (unsigned)(mi * 16 * 144 + kt * 32));
            uint bfr[2][4];
#pragma unroll
            for (int nh = 0; nh < 2; nh++)
                ldsm_x4t(bfr[nh][0], bfr[nh][1], bfr[nh][2], bfr[nh][3],
                         bCol + (unsigned)(kt * 16 * 272 + nh * 32));
#pragma unroll
            for (int nh = 0; nh < 2; nh++)
#pragma unroll
                for (int hf = 0; hf < 2; hf++) {
                    int ni = nh * 2 + hf;
                    uint b0 = bfr[nh][hf * 2], b1 = bfr[nh][hf * 2 + 1];
#pragma unroll
                    for (int mi = 0; mi < 4; mi++)
                        mma_bf16(acc[mi][ni], afr[mi][0], afr[mi][1], afr[mi][2], afr[mi][3], b0, b1);
                }
        }
        __syncthreads();
    }

    // ---- epilogue ----
#pragma unroll
    for (int mi = 0; mi < 4; mi++) {
#pragma unroll
        for (int ni = 0; ni < 4; ni++) {
            int r0 = bm + mBase + mi * 16 + grp;
            int c0 = bn + nBase + ni * 8 + tig * 2;
            float bv0 = (bias && c0     < N) ? bias[c0]     : 0.f;
            float bv1 = (bias && c0 + 1 < N) ? bias[c0 + 1] : 0.f;
            if (r0 < M) {
                if (c0     < N) C[(long)r0 * N + c0]     = acc[mi][ni][0] + bv0;
                if (c0 + 1 < N) C[(long)r0 * N + c0 + 1] = acc[mi][ni][1] + bv1;
            }
            int r1 = r0 + 8;
            if (r1 < M) {
                if (c0     < N) C[(long)r1 * N + c0]     = acc[mi][ni][2] + bv0;
                if (c0 + 1 < N) C[(long)r1 * N + c0 + 1] = acc[mi][ni][3] + bv1;
            }
        }
    }
}

// =====================================================================
// Tensor-core LSTM recurrence, cluster of 8 CTAs, 256 threads (8 warps).
// Rank r owns 128 z-cols (j=g*32+u -> global g*256+r*32+u); warp w owns
// n-slice [w*16, w*16+16); U frags resident in registers (64 regs).
// h double-buffered bf16 in SMEM; per-step sync = per-CTA mbarrier with
// 8 remote release-arrives.
// =====================================================================
template<int BSUB, bool WRITE_HS>
__device__ __forceinline__ void lstm_body_tc(
    const float* __restrict__ Z, const float* __restrict__ U,
    void* __restrict__ OUT, int sbase, int dir, int zstride)
{
    constexpr int CELLN = BSUB * 16;
    __shared__ __align__(16) unsigned short hb[2][16][264];  // 528B rows
    __shared__ __align__(16) float zbuf[8][132];
    __shared__ __align__(8) unsigned long long mbar;

    const int tid = threadIdx.x;
    const int warp = tid >> 5, lane = tid & 31;
    const int tig = lane & 3, grp = lane >> 2;
    const unsigned r = ctarank();
    const int nbase = warp * 16;

    // ---- resident recurrent-weight fragments ----
    uint BF[16][2][2];
#pragma unroll
    for (int kt = 0; kt < 16; kt++) {
#pragma unroll
        for (int nt = 0; nt < 2; nt++) {
            int n = nbase + nt * 8 + grp;
            int c = ((n >> 5) << 8) + (int)r * 32 + (n & 31);
            int k0 = kt * 16 + tig * 2;
            BF[kt][nt][0] = pack2bf(U[(long)(k0    ) * 1024 + c], U[(long)(k0 + 1) * 1024 + c]);
            BF[kt][nt][1] = pack2bf(U[(long)(k0 + 8) * 1024 + c], U[(long)(k0 + 9) * 1024 + c]);
        }
    }
    uint* hbw = (uint*)&hb[0][0][0];
    for (int i = tid; i < 2 * 16 * 132; i += 256) hbw[i] = 0;
    const unsigned mbar_s = (unsigned)__cvta_generic_to_shared(&mbar);
    if (tid == 0)
        asm volatile("mbarrier.init.shared.b64 [%0], 8;" :: "r"(mbar_s) : "memory");
    __syncthreads();
    cluster_sync_all();

    const bool is_cell = tid < CELLN;
    const int cs = tid >> 4;
    const int up = tid & 15;
    const int u2 = up * 2;
    float cst0 = 0.f, cst1 = 0.f;
    const unsigned hb_s = (unsigned)__cvta_generic_to_shared(&hb[0][0][0]);
    const float* zr0 = Z + (long)(sbase + cs) * Tn * zstride + (int)r * 32 + u2;

    for (int step = 0; step < Tn; ++step) {
        const int cur = step & 1, nxt = cur ^ 1;
        const int t = dir ? (Tn - 1 - step) : step;

        float2 zin[4];
        if (is_cell) {
            const float* zr = zr0 + (long)t * zstride;
#pragma unroll
            for (int g = 0; g < 4; g++) zin[g] = *(const float2*)(zr + (g << 8));
        }
        if (step > 0) mbar_wait(mbar_s, (unsigned)((step - 1) & 1));

        // ---- z = h @ U : 4 independent 8-deep HMMA chains ----
        float a0c[4] = {0,0,0,0}, a1c[4] = {0,0,0,0};
        float a0d[4] = {0,0,0,0}, a1d[4] = {0,0,0,0};
        unsigned hrow = hb_s + (unsigned)((cur * 16 + (lane & 15)) * 528)
                             + (unsigned)((lane >> 4) << 4);
#pragma unroll
        for (int kt = 0; kt < 16; kt += 2) {
            uint x0, x1, x2, x3;
            ldsm_x4(x0, x1, x2, x3, hrow + (unsigned)(kt * 32));
            mma_bf16(a0c, x0, x1, x2, x3, BF[kt][0][0], BF[kt][0][1]);
            mma_bf16(a1c, x0, x1, x2, x3, BF[kt][1][0], BF[kt][1][1]);
            uint y0, y1, y2, y3;
            ldsm_x4(y0, y1, y2, y3, hrow + (unsigned)(kt * 32 + 32));
            mma_bf16(a0d, y0, y1, y2, y3, BF[kt + 1][0][0], BF[kt + 1][0][1]);
            mma_bf16(a1d, y0, y1, y2, y3, BF[kt + 1][1][0], BF[kt + 1][1][1]);
        }
        *(float2*)&zbuf[grp][nbase + tig * 2] =
            make_float2(a0c[0] + a0d[0], a0c[1] + a0d[1]);
        *(float2*)&zbuf[grp][nbase + 8 + tig * 2] =
            make_float2(a1c[0] + a1d[0], a1c[1] + a1d[1]);
        __syncthreads();

        // ---- cell update (2 units per thread) ----
        if (is_cell) {
            float zi0 = zbuf[cs][     u2] + zin[0].x, zi1 = zbuf[cs][     u2 + 1] + zin[0].y;
            float zf0 = zbuf[cs][32 + u2] + zin[1].x, zf1 = zbuf[cs][32 + u2 + 1] + zin[1].y;
            float zg0 = zbuf[cs][64 + u2] + zin[2].x, zg1 = zbuf[cs][64 + u2 + 1] + zin[2].y;
            float zo0 = zbuf[cs][96 + u2] + zin[3].x, zo1 = zbuf[cs][96 + u2 + 1] + zin[3].y;
            cst0 = sigmoidf_(zf0) * cst0 + sigmoidf_(zi0) * fmaxf(zg0, 0.f);
            cst1 = sigmoidf_(zf1) * cst1 + sigmoidf_(zi1) * fmaxf(zg1, 0.f);
            float h0 = sigmoidf_(zo0) * fmaxf(cst0, 0.f);
            float h1 = sigmoidf_(zo1) * fmaxf(cst1, 0.f);
            uint hv = pack2bf(h0, h1);

            if (step < Tn - 1) {
                unsigned loff = hb_s + (unsigned)((nxt * 16 + cs) * 132 + (int)r * 16 + up) * 4u;
#pragma unroll
                for (unsigned tr = 0; tr < 8; tr++) st_cluster_u32(loff, tr, hv);
            }
            if (WRITE_HS) {
                *(uint*)((__nv_bfloat16*)OUT +
                         ((long)(sbase + cs) * Tn + t) * 512 + dir * 256 + (int)r * 32 + u2) = hv;
            } else if (step == Tn - 1) {
                float* o = (float*)OUT + (sbase + cs) * 256 + (int)r * 32 + u2;
                o[0] = h0; o[1] = h1;
            }
            if (step < Tn - 1) {
                asm volatile("bar.sync 1, %0;" :: "r"(CELLN) : "memory");
                if (tid < 8) mbar_arrive_remote(mbar_s, (unsigned)tid);
            }
        }
    }
    cluster_sync_all();
}

__global__ void __cluster_dims__(8, 1, 1) __launch_bounds__(256, 1)
lstm1_kernel(const float* __restrict__ Zcat,
             const float* __restrict__ Uf, const float* __restrict__ Ub,
             __nv_bfloat16* __restrict__ HS)
{
    int cid = blockIdx.x >> 3;
    int dir = cid >> 3;
    int cl  = cid & 7;
    lstm_body_tc<8, true>(Zcat + dir * 1024, dir ? Ub : Uf, HS, cl * 8, dir, 2048);
}

__global__ void __cluster_dims__(8, 1, 1) __launch_bounds__(256, 1)
lstm2_kernel(const float* __restrict__ Z, const float* __restrict__ U,
             float* __restrict__ HL)
{
    int cid = blockIdx.x >> 3;
    lstm_body_tc<4, false>(Z, U, HL, cid * 4, 0, 1024);
}

// =====================================================================
// Dense head + softmax
// =====================================================================
__global__ __launch_bounds__(256) void dense3_kernel(
    const float* __restrict__ HL, const float* __restrict__ W3,
    const float* __restrict__ b3, __nv_bfloat16* __restrict__ D3bf)
{
    __shared__ float h[256];
    int s = blockIdx.x;
    h[threadIdx.x] = HL[s * 256 + threadIdx.x];
    __syncthreads();
    for (int j = threadIdx.x; j < U3n; j += 256) {
        float acc = b3[j];
#pragma unroll 8
        for (int k = 0; k < 256; k++) acc = fmaf(h[k], W3[k * U3n + j], acc);
        D3bf[s * U3n + j] = __float2bfloat16_rn(fmaxf(acc, 0.f));
    }
}

__global__ __launch_bounds__(256) void softmax_kernel(float* __restrict__ X)
{
    __shared__ float red[256];
    float* x = X + (long)blockIdx.x * U4n;
    int tid = threadIdx.x;

    float m = -1e30f;
    for (int j = tid; j < U4n; j += 256) m = fmaxf(m, x[j]);
    red[tid] = m; __syncthreads();
    for (int s = 128; s > 0; s >>= 1) {
        if (tid < s) red[tid] = fmaxf(red[tid], red[tid + s]);
        __syncthreads();
    }
    m = red[0]; __syncthreads();

    float sum = 0.f;
    for (int j = tid; j < U4n; j += 256) {
        float e = __expf(x[j] - m);
        x[j] = e;
        sum += e;
    }
    red[tid] = sum; __syncthreads();
    for (int s = 128; s > 0; s >>= 1) {
        if (tid < s) red[tid] += red[tid + s];
        __syncthreads();
    }
    float inv = 1.f / red[0];
    __syncthreads();
    for (int j = tid; j < U4n; j += 256) x[j] *= inv;
}

// =====================================================================
// launcher
// =====================================================================
extern "C" void kernel_launch(void* const* d_in, const int* in_sizes, int n_in,
                              void* d_out, int out_size)
{
    const int*   tokens = (const int*)  d_in[0];
    const float* emb    = (const float*)d_in[1];
    const float* W1f    = (const float*)d_in[2];
    const float* U1f    = (const float*)d_in[3];
    const float* b1f    = (const float*)d_in[4];
    const float* W1b    = (const float*)d_in[5];
    const float* U1b    = (const float*)d_in[6];
    const float* b1b    = (const float*)d_in[7];
    const float* W2     = (const float*)d_in[8];
    const float* U2m    = (const float*)d_in[9];
    const float* b2     = (const float*)d_in[10];
    const float* W3     = (const float*)d_in[11];
    const float* b3     = (const float*)d_in[12];
    const float* W4     = (const float*)d_in[13];
    const float* b4     = (const float*)d_in[14];
    float* out = (float*)d_out;

    float *Z1cat, *Z2, *HL, *bcat;
    __nv_bfloat16 *HS, *D3bf, *Xbf, *W1cat, *W2_bf, *W4_bf;
    cudaGetSymbolAddress((void**)&Z1cat, g_Z1cat);
    cudaGetSymbolAddress((void**)&Z2,    g_Z2);
    cudaGetSymbolAddress((void**)&HS,    g_HS);
    cudaGetSymbolAddress((void**)&HL,    g_HL);
    cudaGetSymbolAddress((void**)&D3bf,  g_D3bf);
    cudaGetSymbolAddress((void**)&Xbf,   g_Xbf);
    cudaGetSymbolAddress((void**)&W1cat, g_W1cat);
    cudaGetSymbolAddress((void**)&bcat,  g_bcat);
    cudaGetSymbolAddress((void**)&W2_bf, g_W2_bf);
    cudaGetSymbolAddress((void**)&W4_bf, g_W4_bf);

    cudaFuncSetAttribute((const void*)gemm_bf16_v3,
                         cudaFuncAttributeMaxDynamicSharedMemorySize, GEMM_SMEM);

    // 0: fused gather+convert of used embedding rows
    gatherconv_kernel<<<2048, 256>>>(emb, tokens, Xbf);
    // 1: concat + convert LSTM1 input weights (+ bias)
    convcat_kernel<<<256, 256>>>(W1f, W1b, b1f, b1b, W1cat, bcat);
    // 2,3: remaining weight conversions
    f2bf_kernel<<<512,  256>>>(W2, W2_bf, 512 * 1024 / 4);
    f2bf_kernel<<<1024, 256>>>(W4, W4_bf, 512 * U4n / 4);

    // 4: fused LSTM1 input projection (fw|bw)
    {
        dim3 grid(16, 128);
        gemm_bf16_v3<<<grid, 256, GEMM_SMEM>>>(Xbf, W1cat, bcat, Z1cat,
                                               ROWS, 2048, En, En);
    }
    // 5: BiLSTM layer 1  (ncu -s 5 -c 1 captures this launch)
    lstm1_kernel<<<128, 256>>>(Z1cat, U1f, U1b, HS);
    // 6: LSTM2 input projection
    {
        dim3 grid(8, 128);
        gemm_bf16_v3<<<grid, 256, GEMM_SMEM>>>(HS, W2_bf, b2, Z2,
                                               ROWS, 1024, 512, 512);
    }
    // 7: LSTM2 (h_last only)
    lstm2_kernel<<<128, 256>>>(Z2, U2m, HL);
    // 8: dense relu -> bf16
    dense3_kernel<<<Bn, 256>>>(HL, W3, b3, D3bf);
    // 9: logits GEMM into d_out
    {
        dim3 grid((U4n + 127) / 128, 1);
        gemm_bf16_v3<<<grid, 256, GEMM_SMEM>>>(D3bf, W4_bf, b4, out,
                                               Bn, U4n, U3n, U3n);
    }
    // 10: softmax in place
    softmax_kernel<<<Bn, 256>>>(out);
}

// round 6
// speedup vs baseline: 2.7426x; 1.0323x over previous
#include <cuda_runtime.h>
#include <cuda_bf16.h>
#include <cstdint>

typedef unsigned int uint;

// ---------------- problem constants ----------------
#define Bn   64
#define Tn   256
#define En   128
#define H1   256
#define H2   256
#define U3n  512
#define U4n  5000
#define ROWS (Bn*Tn)      // 16384

// ---------------- scratch ----------------
__device__ float g_Z1cat[ROWS * 2048];            // fw cols 0..1023, bw 1024..2047
__device__ float g_Z2 [ROWS * 1024];
__device__ __nv_bfloat16 g_HS[ROWS * 512];
__device__ float g_HL [Bn * H2];
__device__ __nv_bfloat16 g_D3bf[Bn * U3n];
__device__ __nv_bfloat16 g_Xbf[ROWS * En];        // gathered+converted embeddings
__device__ __nv_bfloat16 g_W1cat[En * 2048];
__device__ float g_bcat[2048];
__device__ __nv_bfloat16 g_W2_bf [512 * 1024];
__device__ __nv_bfloat16 g_W4_bf [512 * U4n];
__device__ uint2 g_Upk[3 * 65536];                // packed U frags: U1f, U1b, U2m

// ---------------- helpers ----------------
__device__ __forceinline__ unsigned ctarank() {
    unsigned r; asm("mov.u32 %0, %%cluster_ctarank;" : "=r"(r)); return r;
}
__device__ __forceinline__ void cluster_sync_all() {
    asm volatile("barrier.cluster.arrive.aligned;\n\tbarrier.cluster.wait.aligned;" ::: "memory");
}
__device__ __forceinline__ void st_cluster_u32(unsigned local_addr, unsigned rank, uint v) {
    unsigned ra;
    asm volatile("mapa.shared::cluster.u32 %0, %1, %2;" : "=r"(ra) : "r"(local_addr), "r"(rank));
    asm volatile("st.shared::cluster.b32 [%0], %1;" :: "r"(ra), "r"(v) : "memory");
}
__device__ __forceinline__ void mbar_arrive_remote(unsigned local_mbar, unsigned rank) {
    unsigned ra;
    asm volatile("mapa.shared::cluster.u32 %0, %1, %2;" : "=r"(ra) : "r"(local_mbar), "r"(rank));
    asm volatile("mbarrier.arrive.release.cluster.shared::cluster.b64 _, [%0];" :: "r"(ra) : "memory");
}
__device__ __forceinline__ void mbar_wait(unsigned addr, unsigned parity) {
    asm volatile(
        "{\n\t.reg .pred P;\n"
        "LW_%=:\n\t"
        "mbarrier.try_wait.parity.acquire.cluster.shared::cta.b64 P, [%0], %1;\n\t"
        "@P bra LD_%=;\n\t"
        "bra LW_%=;\n"
        "LD_%=:\n\t}"
        :: "r"(addr), "r"(parity) : "memory");
}
__device__ __forceinline__ uint pack2bf(float a, float b) {
    __nv_bfloat162 t = __floats2bfloat162_rn(a, b);
    return *(uint*)&t;
}
__device__ __forceinline__ void mma_bf16(float* d,
                                         uint a0, uint a1, uint a2, uint a3,
                                         uint b0, uint b1) {
    asm volatile("mma.sync.aligned.m16n8k16.row.col.f32.bf16.bf16.f32 "
                 "{%0,%1,%2,%3},{%4,%5,%6,%7},{%8,%9},{%0,%1,%2,%3};"
                 : "+f"(d[0]), "+f"(d[1]), "+f"(d[2]), "+f"(d[3])
                 : "r"(a0), "r"(a1), "r"(a2), "r"(a3), "r"(b0), "r"(b1));
}
__device__ __forceinline__ void ldsm_x4(uint& r0, uint& r1, uint& r2, uint& r3, unsigned a) {
    asm volatile("ldmatrix.sync.aligned.m8n8.x4.shared.b16 {%0,%1,%2,%3}, [%4];"
                 : "=r"(r0), "=r"(r1), "=r"(r2), "=r"(r3) : "r"(a));
}
__device__ __forceinline__ void ldsm_x4t(uint& r0, uint& r1, uint& r2, uint& r3, unsigned a) {
    asm volatile("ldmatrix.sync.aligned.m8n8.x4.trans.shared.b16 {%0,%1,%2,%3}, [%4];"
                 : "=r"(r0), "=r"(r1), "=r"(r2), "=r"(r3) : "r"(a));
}
__device__ __forceinline__ void cp_async16(unsigned saddr, const void* gaddr) {
    asm volatile("cp.async.cg.shared.global [%0], [%1], 16;" :: "r"(saddr), "l"(gaddr));
}
__device__ __forceinline__ float sigmoidf_(float z) {
    return 1.0f / (1.0f + __expf(-z));
}

// =====================================================================
// Fused gather + f32->bf16: Xbf[i,:] = bf16(emb[tokens[i],:])
// =====================================================================
__global__ __launch_bounds__(256) void gatherconv_kernel(
    const float* __restrict__ emb, const int* __restrict__ tokens,
    __nv_bfloat16* __restrict__ Xbf)
{
    int u = blockIdx.x * 256 + threadIdx.x;        // 0 .. 16384*32-1
    int row = u >> 5;
    int c4 = (u & 31) << 2;
    long tok = tokens[row];
    float4 v = *(const float4*)&emb[tok * En + c4];
    uint2 w;
    w.x = pack2bf(v.x, v.y);
    w.y = pack2bf(v.z, v.w);
    *(uint2*)&Xbf[(long)row * En + c4] = w;
}

// =====================================================================
// Prep: W1cat concat+convert (+bcat) and packed-U fragment tables.
// grid = 1024 x 256. bid<256: W1cat; bid>=256: Upk (3 x 65536 uint2).
// Packed layout per (which, rank r, warp w): 1024 uint2; entry
// (kt*2+nt)*32 + lane = {pack(U[k0][c],U[k0+1][c]), pack(U[k0+8][c],U[k0+9][c])}
// with tig=lane&3, grp=lane>>2, n=w*16+nt*8+grp, c=(n>>5)*256+r*32+(n&31),
// k0=kt*16+tig*2.
// =====================================================================
__global__ __launch_bounds__(256) void prep_kernel(
    const float* __restrict__ W1f, const float* __restrict__ W1b,
    const float* __restrict__ b1f, const float* __restrict__ b1b,
    const float* __restrict__ U1f, const float* __restrict__ U1b,
    const float* __restrict__ U2m,
    __nv_bfloat16* __restrict__ Wcat, float* __restrict__ bcat,
    uint2* __restrict__ Upk)
{
    int bid = blockIdx.x;
    if (bid < 256) {
        int u = bid * 256 + threadIdx.x;           // 0 .. 65535
        int row = u >> 9;
        int c4 = (u & 511) << 2;
        const float* src = (c4 < 1024) ? &W1f[row * 1024 + c4]
                                       : &W1b[row * 1024 + c4 - 1024];
        float4 v = *(const float4*)src;
        uint2 w;
        w.x = pack2bf(v.x, v.y);
        w.y = pack2bf(v.z, v.w);
        *(uint2*)&Wcat[(long)row * 2048 + c4] = w;
        if (bid == 0) {
            for (int j = threadIdx.x; j < 1024; j += 256) {
                bcat[j] = b1f[j];
                bcat[1024 + j] = b1b[j];
            }
        }
    } else {
        int g = (bid - 256) * 256 + threadIdx.x;   // 0 .. 196607
        int which = g >> 16;
        int idx = g & 65535;
        int lane = idx & 31;
        int rest = idx >> 5;
        int nt = rest & 1;
        int kt = (rest >> 1) & 15;
        int w  = (rest >> 5) & 7;
        int r  = rest >> 8;
        const float* U = (which == 0) ? U1f : (which == 1) ? U1b : U2m;
        int tig = lane & 3, grp = lane >> 2;
        int n = w * 16 + nt * 8 + grp;
        int c = ((n >> 5) << 8) + r * 32 + (n & 31);
        int k0 = kt * 16 + tig * 2;
        uint2 v;
        v.x = pack2bf(U[(long)(k0    ) * 1024 + c], U[(long)(k0 + 1) * 1024 + c]);
        v.y = pack2bf(U[(long)(k0 + 8) * 1024 + c], U[(long)(k0 + 9) * 1024 + c]);
        Upk[g] = v;
    }
}

// =====================================================================
// f32 -> bf16 conversion (vectorized, grid-stride). n % 4 == 0.
// =====================================================================
__global__ __launch_bounds__(256) void f2bf_kernel(
    const float* __restrict__ s, __nv_bfloat16* __restrict__ d, int n4)
{
    int i = blockIdx.x * blockDim.x + threadIdx.x;
    int stride = gridDim.x * blockDim.x;
    for (; i < n4; i += stride) {
        float4 v = ((const float4*)s)[i];
        uint2 w;
        w.x = pack2bf(v.x, v.y);
        w.y = pack2bf(v.z, v.w);
        ((uint2*)d)[i] = w;
    }
}

// =====================================================================
// bf16 GEMM v3:  C[M,N] = A[M,K] @ B[K,N] + bias   (fp32 out)
// 3-stage cp.async pipeline; ldmatrix fragment loads.
// =====================================================================
#define A_STG 18432
#define B_STG 17408
#define B_OFF 55296
#define GEMM_SMEM 107520

__global__ __launch_bounds__(256) void gemm_bf16_v3(
    const __nv_bfloat16* __restrict__ A, const __nv_bfloat16* __restrict__ B,
    const float* __restrict__ bias, float* __restrict__ C,
    int M, int N, int K, int lda)
{
    extern __shared__ char dynsm[];
    const unsigned sbase = (unsigned)__cvta_generic_to_shared(dynsm);

    const int bm = blockIdx.y * 128;
    const int bn = blockIdx.x * 128;
    const int tid = threadIdx.x;
    const int warp = tid >> 5, lane = tid & 31;
    const int wm = warp >> 2, wn = warp & 3;
    const int mBase = wm * 64, nBase = wn * 32;
    const int grp = lane >> 2, tig = lane & 3;

    auto stage = [&](int kb, int st) {
#pragma unroll
        for (int i = 0; i < 4; i++) {
            int idx = tid + i * 256;
            int row = idx >> 3, ch = idx & 7;
            unsigned off = (unsigned)(st * A_STG + row * 144 + ch * 16);
            if (bm + row < M) {
                cp_async16(sbase + off, A + (long)(bm + row) * lda + kb * 64 + ch * 8);
            } else {
                *(uint4*)(dynsm + off) = make_uint4(0, 0, 0, 0);
            }
        }
#pragma unroll
        for (int i = 0; i < 4; i++) {
            int idx = tid + i * 256;
            int k = idx >> 4, ch = idx & 15;
            int gc = bn + ch * 8;
            unsigned off = (unsigned)(B_OFF + st * B_STG + k * 272 + ch * 16);
            if (gc < N) {
                cp_async16(sbase + off, B + (long)(kb * 64 + k) * N + gc);
            } else {
                *(uint4*)(dynsm + off) = make_uint4(0, 0, 0, 0);
            }
        }
        asm volatile("cp.async.commit_group;");
    };

    float acc[4][4][4];
#pragma unroll
    for (int a = 0; a < 4; a++)
#pragma unroll
        for (int b = 0; b < 4; b++)
#pragma unroll
            for (int c = 0; c < 4; c++) acc[a][b][c] = 0.f;

    const int nk = K >> 6;
    stage(0, 0);
    if (nk > 1) stage(1, 1);

    for (int kb = 0; kb < nk; kb++) {
        int st = kb % 3;
        if (kb + 2 < nk) {
            stage(kb + 2, (kb + 2) % 3);
            asm volatile("cp.async.wait_group 2;");
        } else if (kb + 1 < nk) {
            asm volatile("cp.async.wait_group 1;");
        } else {
            asm volatile("cp.async.wait_group 0;");
        }
        __syncthreads();

        unsigned aRow = sbase + (unsigned)(st * A_STG)
                      + (unsigned)((mBase + (lane & 15)) * 144)
                      + (unsigned)((lane >> 4) << 4);
        unsigned bCol = sbase + (unsigned)(B_OFF + st * B_STG)
                      + (unsigned)((lane & 15) * 272)
                      + (unsigned)(nBase * 2 + ((lane >> 4) << 4));

#pragma unroll
        for (int kt = 0; kt < 4; kt++) {
            uint afr[4][4];
#pragma unroll
            for (int mi = 0; mi < 4; mi++)
                ldsm_x4(afr[mi][0], afr[mi][1], afr[mi][2], afr[mi][3],
                        aRow + (unsigned)(mi * 16 * 144 + kt * 32));
            uint bfr[2][4];
#pragma unroll
            for (int nh = 0; nh < 2; nh++)
                ldsm_x4t(bfr[nh][0], bfr[nh][1], bfr[nh][2], bfr[nh][3],
                         bCol + (unsigned)(kt * 16 * 272 + nh * 32));
#pragma unroll
            for (int nh = 0; nh < 2; nh++)
#pragma unroll
                for (int hf = 0; hf < 2; hf++) {
                    int ni = nh * 2 + hf;
                    uint b0 = bfr[nh][hf * 2], b1 = bfr[nh][hf * 2 + 1];
#pragma unroll
                    for (int mi = 0; mi < 4; mi++)
                        mma_bf16(acc[mi][ni], afr[mi][0], afr[mi][1], afr[mi][2], afr[mi][3], b0, b1);
                }
        }
        __syncthreads();
    }

#pragma unroll
    for (int mi = 0; mi < 4; mi++) {
#pragma unroll
        for (int ni = 0; ni < 4; ni++) {
            int r0 = bm + mBase + mi * 16 + grp;
            int c0 = bn + nBase + ni * 8 + tig * 2;
            float bv0 = (bias && c0     < N) ? bias[c0]     : 0.f;
            float bv1 = (bias && c0 + 1 < N) ? bias[c0 + 1] : 0.f;
            if (r0 < M) {
                if (c0     < N) C[(long)r0 * N + c0]     = acc[mi][ni][0] + bv0;
                if (c0 + 1 < N) C[(long)r0 * N + c0 + 1] = acc[mi][ni][1] + bv1;
            }
            int r1 = r0 + 8;
            if (r1 < M) {
                if (c0     < N) C[(long)r1 * N + c0]     = acc[mi][ni][2] + bv0;
                if (c0 + 1 < N) C[(long)r1 * N + c0 + 1] = acc[mi][ni][3] + bv1;
            }
        }
    }
}

// =====================================================================
// Tensor-core LSTM recurrence, cluster of 8 CTAs, 256 threads (8 warps).
// U fragments from pre-packed table (32 coalesced uint2 loads).
// Z prefetched one full step ahead (znx) to hide DRAM latency.
// Per-step sync: per-CTA mbarrier, 8 remote release-arrives.
// =====================================================================
template<int BSUB, bool WRITE_HS>
__device__ __forceinline__ void lstm_body_tc(
    const float* __restrict__ Z, const uint2* __restrict__ Upk,
    void* __restrict__ OUT, int sbase, int dir, int zstride)
{
    constexpr int CELLN = BSUB * 16;
    __shared__ __align__(16) unsigned short hb[2][16][264];  // 528B rows
    __shared__ __align__(16) float zbuf[8][132];
    __shared__ __align__(8) unsigned long long mbar;

    const int tid = threadIdx.x;
    const int warp = tid >> 5, lane = tid & 31;
    const int tig = lane & 3, grp = lane >> 2;
    const unsigned r = ctarank();
    const int nbase = warp * 16;

    // ---- resident recurrent-weight fragments (coalesced packed load) ----
    uint BF[16][2][2];
    {
        const uint2* up = Upk + (((int)r * 8 + warp) << 10) + lane;
#pragma unroll
        for (int kt = 0; kt < 16; kt++)
#pragma unroll
            for (int nt = 0; nt < 2; nt++) {
                uint2 v = up[(kt * 2 + nt) << 5];
                BF[kt][nt][0] = v.x;
                BF[kt][nt][1] = v.y;
            }
    }
    uint* hbw = (uint*)&hb[0][0][0];
    for (int i = tid; i < 2 * 16 * 132; i += 256) hbw[i] = 0;
    const unsigned mbar_s = (unsigned)__cvta_generic_to_shared(&mbar);
    if (tid == 0)
        asm volatile("mbarrier.init.shared.b64 [%0], 8;" :: "r"(mbar_s) : "memory");
    __syncthreads();
    cluster_sync_all();

    const bool is_cell = tid < CELLN;
    const int cs = tid >> 4;
    const int up2 = tid & 15;
    const int u2 = up2 * 2;
    float cst0 = 0.f, cst1 = 0.f;
    const unsigned hb_s = (unsigned)__cvta_generic_to_shared(&hb[0][0][0]);
    const float* zr0 = Z + (long)(sbase + cs) * Tn * zstride + (int)r * 32 + u2;

    // prime z for step 0
    float2 zin[4];
    if (is_cell) {
        const float* zr = zr0 + (long)(dir ? Tn - 1 : 0) * zstride;
#pragma unroll
        for (int g = 0; g < 4; g++) zin[g] = *(const float2*)(zr + (g << 8));
    }

    for (int step = 0; step < Tn; ++step) {
        const int cur = step & 1, nxt = cur ^ 1;
        const int t = dir ? (Tn - 1 - step) : step;

        // prefetch NEXT step's z (full step of latency cover)
        float2 znx[4];
        if (is_cell && step + 1 < Tn) {
            const int tn = dir ? (Tn - 2 - step) : (step + 1);
            const float* zr = zr0 + (long)tn * zstride;
#pragma unroll
            for (int g = 0; g < 4; g++) znx[g] = *(const float2*)(zr + (g << 8));
        }
        if (step > 0) mbar_wait(mbar_s, (unsigned)((step - 1) & 1));

        // ---- z = h @ U : 4 independent 8-deep HMMA chains ----
        float a0c[4] = {0,0,0,0}, a1c[4] = {0,0,0,0};
        float a0d[4] = {0,0,0,0}, a1d[4] = {0,0,0,0};
        unsigned hrow = hb_s + (unsigned)((cur * 16 + (lane & 15)) * 528)
                             + (unsigned)((lane >> 4) << 4);
#pragma unroll
        for (int kt = 0; kt < 16; kt += 2) {
            uint x0, x1, x2, x3;
            ldsm_x4(x0, x1, x2, x3, hrow + (unsigned)(kt * 32));
            mma_bf16(a0c, x0, x1, x2, x3, BF[kt][0][0], BF[kt][0][1]);
            mma_bf16(a1c, x0, x1, x2, x3, BF[kt][1][0], BF[kt][1][1]);
            uint y0, y1, y2, y3;
            ldsm_x4(y0, y1, y2, y3, hrow + (unsigned)(kt * 32 + 32));
            mma_bf16(a0d, y0, y1, y2, y3, BF[kt + 1][0][0], BF[kt + 1][0][1]);
            mma_bf16(a1d, y0, y1, y2, y3, BF[kt + 1][1][0], BF[kt + 1][1][1]);
        }
        *(float2*)&zbuf[grp][nbase + tig * 2] =
            make_float2(a0c[0] + a0d[0], a0c[1] + a0d[1]);
        *(float2*)&zbuf[grp][nbase + 8 + tig * 2] =
            make_float2(a1c[0] + a1d[0], a1c[1] + a1d[1]);
        __syncthreads();

        // ---- cell update (2 units per thread) ----
        if (is_cell) {
            float zi0 = zbuf[cs][     u2] + zin[0].x, zi1 = zbuf[cs][     u2 + 1] + zin[0].y;
            float zf0 = zbuf[cs][32 + u2] + zin[1].x, zf1 = zbuf[cs][32 + u2 + 1] + zin[1].y;
            float zg0 = zbuf[cs][64 + u2] + zin[2].x, zg1 = zbuf[cs][64 + u2 + 1] + zin[2].y;
            float zo0 = zbuf[cs][96 + u2] + zin[3].x, zo1 = zbuf[cs][96 + u2 + 1] + zin[3].y;
            cst0 = sigmoidf_(zf0) * cst0 + sigmoidf_(zi0) * fmaxf(zg0, 0.f);
            cst1 = sigmoidf_(zf1) * cst1 + sigmoidf_(zi1) * fmaxf(zg1, 0.f);
            float h0 = sigmoidf_(zo0) * fmaxf(cst0, 0.f);
            float h1 = sigmoidf_(zo1) * fmaxf(cst1, 0.f);
            uint hv = pack2bf(h0, h1);

            if (step < Tn - 1) {
                unsigned loff = hb_s + (unsigned)((nxt * 16 + cs) * 132 + (int)r * 16 + up2) * 4u;
#pragma unroll
                for (unsigned tr = 0; tr < 8; tr++) st_cluster_u32(loff, tr, hv);
            }
            if (WRITE_HS) {
                *(uint*)((__nv_bfloat16*)OUT +
                         ((long)(sbase + cs) * Tn + t) * 512 + dir * 256 + (int)r * 32 + u2) = hv;
            } else if (step == Tn - 1) {
                float* o = (float*)OUT + (sbase + cs) * 256 + (int)r * 32 + u2;
                o[0] = h0; o[1] = h1;
            }
#pragma unroll
            for (int g = 0; g < 4; g++) zin[g] = znx[g];
            if (step < Tn - 1) {
                asm volatile("bar.sync 1, %0;" :: "r"(CELLN) : "memory");
                if (tid < 8) mbar_arrive_remote(mbar_s, (unsigned)tid);
            }
        }
    }
    cluster_sync_all();
}

__global__ void __cluster_dims__(8, 1, 1) __launch_bounds__(256, 1)
lstm1_kernel(const float* __restrict__ Zcat, const uint2* __restrict__ Upk,
             __nv_bfloat16* __restrict__ HS)
{
    int cid = blockIdx.x >> 3;
    int dir = cid >> 3;
    int cl  = cid & 7;
    lstm_body_tc<8, true>(Zcat + dir * 1024, Upk + dir * 65536, HS, cl * 8, dir, 2048);
}

__global__ void __cluster_dims__(8, 1, 1) __launch_bounds__(256, 1)
lstm2_kernel(const float* __restrict__ Z, const uint2* __restrict__ Upk,
             float* __restrict__ HL)
{
    int cid = blockIdx.x >> 3;
    lstm_body_tc<4, false>(Z, Upk + 2 * 65536, HL, cid * 4, 0, 1024);
}

// =====================================================================
// Dense head + softmax
// =====================================================================
__global__ __launch_bounds__(256) void dense3_kernel(
    const float* __restrict__ HL, const float* __restrict__ W3,
    const float* __restrict__ b3, __nv_bfloat16* __restrict__ D3bf)
{
    __shared__ float h[256];
    int s = blockIdx.x;
    h[threadIdx.x] = HL[s * 256 + threadIdx.x];
    __syncthreads();
    for (int j = threadIdx.x; j < U3n; j += 256) {
        float acc = b3[j];
#pragma unroll 8
        for (int k = 0; k < 256; k++) acc = fmaf(h[k], W3[k * U3n + j], acc);
        D3bf[s * U3n + j] = __float2bfloat16_rn(fmaxf(acc, 0.f));
    }
}

__global__ __launch_bounds__(256) void softmax_kernel(float* __restrict__ X)
{
    __shared__ float red[256];
    float* x = X + (long)blockIdx.x * U4n;
    int tid = threadIdx.x;

    float m = -1e30f;
    for (int j = tid; j < U4n; j += 256) m = fmaxf(m, x[j]);
    red[tid] = m; __syncthreads();
    for (int s = 128; s > 0; s >>= 1) {
        if (tid < s) red[tid] = fmaxf(red[tid], red[tid + s]);
        __syncthreads();
    }
    m = red[0]; __syncthreads();

    float sum = 0.f;
    for (int j = tid; j < U4n; j += 256) {
        float e = __expf(x[j] - m);
        x[j] = e;
        sum += e;
    }
    red[tid] = sum; __syncthreads();
    for (int s = 128; s > 0; s >>= 1) {
        if (tid < s) red[tid] += red[tid + s];
        __syncthreads();
    }
    float inv = 1.f / red[0];
    __syncthreads();
    for (int j = tid; j < U4n; j += 256) x[j] *= inv;
}

// =====================================================================
// launcher
// =====================================================================
extern "C" void kernel_launch(void* const* d_in, const int* in_sizes, int n_in,
                              void* d_out, int out_size)
{
    const int*   tokens = (const int*)  d_in[0];
    const float* emb    = (const float*)d_in[1];
    const float* W1f    = (const float*)d_in[2];
    const float* U1f    = (const float*)d_in[3];
    const float* b1f    = (const float*)d_in[4];
    const float* W1b    = (const float*)d_in[5];
    const float* U1b    = (const float*)d_in[6];
    const float* b1b    = (const float*)d_in[7];
    const float* W2     = (const float*)d_in[8];
    const float* U2m    = (const float*)d_in[9];
    const float* b2     = (const float*)d_in[10];
    const float* W3     = (const float*)d_in[11];
    const float* b3     = (const float*)d_in[12];
    const float* W4     = (const float*)d_in[13];
    const float* b4     = (const float*)d_in[14];
    float* out = (float*)d_out;

    float *Z1cat, *Z2, *HL, *bcat;
    __nv_bfloat16 *HS, *D3bf, *Xbf, *W1cat, *W2_bf, *W4_bf;
    uint2* Upk;
    cudaGetSymbolAddress((void**)&Z1cat, g_Z1cat);
    cudaGetSymbolAddress((void**)&Z2,    g_Z2);
    cudaGetSymbolAddress((void**)&HS,    g_HS);
    cudaGetSymbolAddress((void**)&HL,    g_HL);
    cudaGetSymbolAddress((void**)&D3bf,  g_D3bf);
    cudaGetSymbolAddress((void**)&Xbf,   g_Xbf);
    cudaGetSymbolAddress((void**)&W1cat, g_W1cat);
    cudaGetSymbolAddress((void**)&bcat,  g_bcat);
    cudaGetSymbolAddress((void**)&W2_bf, g_W2_bf);
    cudaGetSymbolAddress((void**)&W4_bf, g_W4_bf);
    cudaGetSymbolAddress((void**)&Upk,   g_Upk);

    cudaFuncSetAttribute((const void*)gemm_bf16_v3,
                         cudaFuncAttributeMaxDynamicSharedMemorySize, GEMM_SMEM);

    // 0: fused gather+convert of used embedding rows
    gatherconv_kernel<<<2048, 256>>>(emb, tokens, Xbf);
    // 1: all weight prep for LSTM1/LSTM2 (W1cat, bcat, packed U tables)
    prep_kernel<<<1024, 256>>>(W1f, W1b, b1f, b1b, U1f, U1b, U2m, W1cat, bcat, Upk);
    // 2: fused LSTM1 input projection (fw|bw)
    {
        dim3 grid(16, 128);
        gemm_bf16_v3<<<grid, 256, GEMM_SMEM>>>(Xbf, W1cat, bcat, Z1cat,
                                               ROWS, 2048, En, En);
    }
    // 3: BiLSTM layer 1  (profiled launch)
    lstm1_kernel<<<128, 256>>>(Z1cat, Upk, HS);
    // 4,5: head weight conversions (consumed at launches 6 and 9)
    f2bf_kernel<<<512,  256>>>(W2, W2_bf, 512 * 1024 / 4);
    f2bf_kernel<<<1024, 256>>>(W4, W4_bf, 512 * U4n / 4);
    // 6: LSTM2 input projection
    {
        dim3 grid(8, 128);
        gemm_bf16_v3<<<grid, 256, GEMM_SMEM>>>(HS, W2_bf, b2, Z2,
                                               ROWS, 1024, 512, 512);
    }
    // 7: LSTM2 (h_last only)
    lstm2_kernel<<<128, 256>>>(Z2, Upk, HL);
    // 8: dense relu -> bf16
    dense3_kernel<<<Bn, 256>>>(HL, W3, b3, D3bf);
    // 9: logits GEMM into d_out
    {
        dim3 grid((U4n + 127) / 128, 1);
        gemm_bf16_v3<<<grid, 256, GEMM_SMEM>>>(D3bf, W4_bf, b4, out,
                                               Bn, U4n, U3n, U3n);
    }
    // 10: softmax in place
    softmax_kernel<<<Bn, 256>>>(out);
}

// round 7
// speedup vs baseline: 2.7679x; 1.0092x over previous
#include <cuda_runtime.h>
#include <cuda_bf16.h>
#include <cstdint>

typedef unsigned int uint;

// ---------------- problem constants ----------------
#define Bn   64
#define Tn   256
#define En   128
#define H1   256
#define H2   256
#define U3n  512
#define U4n  5000
#define ROWS (Bn*Tn)      // 16384

// ---------------- scratch ----------------
__device__ float g_Z1cat[ROWS * 2048];            // fw cols 0..1023, bw 1024..2047
__device__ float g_Z2 [ROWS * 1024];
__device__ __nv_bfloat16 g_HS[ROWS * 512];
__device__ float g_HL [Bn * H2];
__device__ __nv_bfloat16 g_D3bf[Bn * U3n];
__device__ __nv_bfloat16 g_Xbf[ROWS * En];        // gathered+converted embeddings
__device__ __nv_bfloat16 g_W1cat[En * 2048];
__device__ float g_bcat[2048];
__device__ __nv_bfloat16 g_W2_bf [512 * 1024];
__device__ __nv_bfloat16 g_W4_bf [512 * U4n];
__device__ uint2 g_Upk[3 * 65536];                // packed U frags: U1f, U1b, U2m

// ---------------- helpers ----------------
__device__ __forceinline__ unsigned ctarank() {
    unsigned r; asm("mov.u32 %0, %%cluster_ctarank;" : "=r"(r)); return r;
}
__device__ __forceinline__ void cluster_sync_all() {
    asm volatile("barrier.cluster.arrive.aligned;\n\tbarrier.cluster.wait.aligned;" ::: "memory");
}
__device__ __forceinline__ unsigned mapa_addr(unsigned a, unsigned rank) {
    unsigned ra;
    asm volatile("mapa.shared::cluster.u32 %0, %1, %2;" : "=r"(ra) : "r"(a), "r"(rank));
    return ra;
}
__device__ __forceinline__ void st_async_u32(unsigned daddr, uint v, unsigned mb) {
    asm volatile("st.async.shared::cluster.mbarrier::complete_tx::bytes.b32 [%0], %1, [%2];"
                 :: "r"(daddr), "r"(v), "r"(mb) : "memory");
}
__device__ __forceinline__ void mbar_init(unsigned mb, unsigned cnt) {
    asm volatile("mbarrier.init.shared.b64 [%0], %1;" :: "r"(mb), "r"(cnt) : "memory");
}
__device__ __forceinline__ void mbar_inval(unsigned mb) {
    asm volatile("mbarrier.inval.shared.b64 [%0];" :: "r"(mb) : "memory");
}
__device__ __forceinline__ void mbar_expect(unsigned mb, unsigned tx) {
    asm volatile("mbarrier.arrive.expect_tx.shared.b64 _, [%0], %1;" :: "r"(mb), "r"(tx) : "memory");
}
__device__ __forceinline__ void mbar_wait(unsigned addr, unsigned parity) {
    asm volatile(
        "{\n\t.reg .pred P;\n"
        "LW_%=:\n\t"
        "mbarrier.try_wait.parity.acquire.cluster.shared::cta.b64 P, [%0], %1;\n\t"
        "@P bra LD_%=;\n\t"
        "bra LW_%=;\n"
        "LD_%=:\n\t}"
        :: "r"(addr), "r"(parity) : "memory");
}
__device__ __forceinline__ uint pack2bf(float a, float b) {
    __nv_bfloat162 t = __floats2bfloat162_rn(a, b);
    return *(uint*)&t;
}
__device__ __forceinline__ void mma_bf16(float* d,
                                         uint a0, uint a1, uint a2, uint a3,
                                         uint b0, uint b1) {
    asm volatile("mma.sync.aligned.m16n8k16.row.col.f32.bf16.bf16.f32 "
                 "{%0,%1,%2,%3},{%4,%5,%6,%7},{%8,%9},{%0,%1,%2,%3};"
                 : "+f"(d[0]), "+f"(d[1]), "+f"(d[2]), "+f"(d[3])
                 : "r"(a0), "r"(a1), "r"(a2), "r"(a3), "r"(b0), "r"(b1));
}
__device__ __forceinline__ void ldsm_x4(uint& r0, uint& r1, uint& r2, uint& r3, unsigned a) {
    asm volatile("ldmatrix.sync.aligned.m8n8.x4.shared.b16 {%0,%1,%2,%3}, [%4];"
                 : "=r"(r0), "=r"(r1), "=r"(r2), "=r"(r3) : "r"(a));
}
__device__ __forceinline__ void ldsm_x4t(uint& r0, uint& r1, uint& r2, uint& r3, unsigned a) {
    asm volatile("ldmatrix.sync.aligned.m8n8.x4.trans.shared.b16 {%0,%1,%2,%3}, [%4];"
                 : "=r"(r0), "=r"(r1), "=r"(r2), "=r"(r3) : "r"(a));
}
__device__ __forceinline__ void cp_async16(unsigned saddr, const void* gaddr) {
    asm volatile("cp.async.cg.shared.global [%0], [%1], 16;" :: "r"(saddr), "l"(gaddr));
}
__device__ __forceinline__ float sigmoidf_(float z) {
    return 1.0f / (1.0f + __expf(-z));
}

// =====================================================================
// Fused gather + f32->bf16: Xbf[i,:] = bf16(emb[tokens[i],:])
// =====================================================================
__global__ __launch_bounds__(256) void gatherconv_kernel(
    const float* __restrict__ emb, const int* __restrict__ tokens,
    __nv_bfloat16* __restrict__ Xbf)
{
    int u = blockIdx.x * 256 + threadIdx.x;        // 0 .. 16384*32-1
    int row = u >> 5;
    int c4 = (u & 31) << 2;
    long tok = tokens[row];
    float4 v = *(const float4*)&emb[tok * En + c4];
    uint2 w;
    w.x = pack2bf(v.x, v.y);
    w.y = pack2bf(v.z, v.w);
    *(uint2*)&Xbf[(long)row * En + c4] = w;
}

// =====================================================================
// Prep: W1cat concat+convert (+bcat) and packed-U fragment tables.
// NEW fragment column mapping (warp-local gate ownership):
//   local col cc = nt*8 + grp  ->  global col (cc&3)*256 + r*32 + w*4 + (cc>>2)
// so warp w's 16 columns = all 4 gates of hidden units r*32+4w .. +3.
// =====================================================================
__global__ __launch_bounds__(256) void prep_kernel(
    const float* __restrict__ W1f, const float* __restrict__ W1b,
    const float* __restrict__ b1f, const float* __restrict__ b1b,
    const float* __restrict__ U1f, const float* __restrict__ U1b,
    const float* __restrict__ U2m,
    __nv_bfloat16* __restrict__ Wcat, float* __restrict__ bcat,
    uint2* __restrict__ Upk)
{
    int bid = blockIdx.x;
    if (bid < 256) {
        int u = bid * 256 + threadIdx.x;           // 0 .. 65535
        int row = u >> 9;
        int c4 = (u & 511) << 2;
        const float* src = (c4 < 1024) ? &W1f[row * 1024 + c4]
                                       : &W1b[row * 1024 + c4 - 1024];
        float4 v = *(const float4*)src;
        uint2 w;
        w.x = pack2bf(v.x, v.y);
        w.y = pack2bf(v.z, v.w);
        *(uint2*)&Wcat[(long)row * 2048 + c4] = w;
        if (bid == 0) {
            for (int j = threadIdx.x; j < 1024; j += 256) {
                bcat[j] = b1f[j];
                bcat[1024 + j] = b1b[j];
            }
        }
    } else {
        int g = (bid - 256) * 256 + threadIdx.x;   // 0 .. 196607
        int which = g >> 16;
        int idx = g & 65535;
        int lane = idx & 31;
        int rest = idx >> 5;
        int nt = rest & 1;
        int kt = (rest >> 1) & 15;
        int w  = (rest >> 5) & 7;
        int r  = rest >> 8;
        const float* U = (which == 0) ? U1f : (which == 1) ? U1b : U2m;
        int tig = lane & 3, grp = lane >> 2;
        int cc = nt * 8 + grp;                     // local col 0..15 in warp slice
        int c = (cc & 3) * 256 + r * 32 + w * 4 + (cc >> 2);
        int k0 = kt * 16 + tig * 2;
        uint2 v;
        v.x = pack2bf(U[(long)(k0    ) * 1024 + c], U[(long)(k0 + 1) * 1024 + c]);
        v.y = pack2bf(U[(long)(k0 + 8) * 1024 + c], U[(long)(k0 + 9) * 1024 + c]);
        Upk[g] = v;
    }
}

// =====================================================================
// f32 -> bf16 conversion (vectorized, grid-stride). n % 4 == 0.
// =====================================================================
__global__ __launch_bounds__(256) void f2bf_kernel(
    const float* __restrict__ s, __nv_bfloat16* __restrict__ d, int n4)
{
    int i = blockIdx.x * blockDim.x + threadIdx.x;
    int stride = gridDim.x * blockDim.x;
    for (; i < n4; i += stride) {
        float4 v = ((const float4*)s)[i];
        uint2 w;
        w.x = pack2bf(v.x, v.y);
        w.y = pack2bf(v.z, v.w);
        ((uint2*)d)[i] = w;
    }
}

// =====================================================================
// bf16 GEMM v3:  C[M,N] = A[M,K] @ B[K,N] + bias   (fp32 out)
// 3-stage cp.async pipeline; ldmatrix fragment loads. (unchanged)
// =====================================================================
#define A_STG 18432
#define B_STG 17408
#define B_OFF 55296
#define GEMM_SMEM 107520

__global__ __launch_bounds__(256) void gemm_bf16_v3(
    const __nv_bfloat16* __restrict__ A, const __nv_bfloat16* __restrict__ B,
    const float* __restrict__ bias, float* __restrict__ C,
    int M, int N, int K, int lda)
{
    extern __shared__ char dynsm[];
    const unsigned sbase = (unsigned)__cvta_generic_to_shared(dynsm);

    const int bm = blockIdx.y * 128;
    const int bn = blockIdx.x * 128;
    const int tid = threadIdx.x;
    const int warp = tid >> 5, lane = tid & 31;
    const int wm = warp >> 2, wn = warp & 3;
    const int mBase = wm * 64, nBase = wn * 32;
    const int grp = lane >> 2, tig = lane & 3;

    auto stage = [&](int kb, int st) {
#pragma unroll
        for (int i = 0; i < 4; i++) {
            int idx = tid + i * 256;
            int row = idx >> 3, ch = idx & 7;
            unsigned off = (unsigned)(st * A_STG + row * 144 + ch * 16);
            if (bm + row < M) {
                cp_async16(sbase + off, A + (long)(bm + row) * lda + kb * 64 + ch * 8);
            } else {
                *(uint4*)(dynsm + off) = make_uint4(0, 0, 0, 0);
            }
        }
#pragma unroll
        for (int i = 0; i < 4; i++) {
            int idx = tid + i * 256;
            int k = idx >> 4, ch = idx & 15;
            int gc = bn + ch * 8;
            unsigned off = (unsigned)(B_OFF + st * B_STG + k * 272 + ch * 16);
            if (gc < N) {
                cp_async16(sbase + off, B + (long)(kb * 64 + k) * N + gc);
            } else {
                *(uint4*)(dynsm + off) = make_uint4(0, 0, 0, 0);
            }
        }
        asm volatile("cp.async.commit_group;");
    };

    float acc[4][4][4];
#pragma unroll
    for (int a = 0; a < 4; a++)
#pragma unroll
        for (int b = 0; b < 4; b++)
#pragma unroll
            for (int c = 0; c < 4; c++) acc[a][b][c] = 0.f;

    const int nk = K >> 6;
    stage(0, 0);
    if (nk > 1) stage(1, 1);

    for (int kb = 0; kb < nk; kb++) {
        int st = kb % 3;
        if (kb + 2 < nk) {
            stage(kb + 2, (kb + 2) % 3);
            asm volatile("cp.async.wait_group 2;");
        } else if (kb + 1 < nk) {
            asm volatile("cp.async.wait_group 1;");
        } else {
            asm volatile("cp.async.wait_group 0;");
        }
        __syncthreads();

        unsigned aRow = sbase + (unsigned)(st * A_STG)
                      + (unsigned)((mBase + (lane & 15)) * 144)
                      + (unsigned)((lane >> 4) << 4);
        unsigned bCol = sbase + (unsigned)(B_OFF + st * B_STG)
                      + (unsigned)((lane & 15) * 272)
                      + (unsigned)(nBase * 2 + ((lane >> 4) << 4));

#pragma unroll
        for (int kt = 0; kt < 4; kt++) {
            uint afr[4][4];
#pragma unroll
            for (int mi = 0; mi < 4; mi++)
                ldsm_x4(afr[mi][0], afr[mi][1], afr[mi][2], afr[mi][3],
                        aRow + (unsigned)(mi * 16 * 144 + kt * 32));
            uint bfr[2][4];
#pragma unroll
            for (int nh = 0; nh < 2; nh++)
                ldsm_x4t(bfr[nh][0], bfr[nh][1], bfr[nh][2], bfr[nh][3],
                         bCol + (unsigned)(kt * 16 * 272 + nh * 32));
#pragma unroll
            for (int nh = 0; nh < 2; nh++)
#pragma unroll
                for (int hf = 0; hf < 2; hf++) {
                    int ni = nh * 2 + hf;
                    uint b0 = bfr[nh][hf * 2], b1 = bfr[nh][hf * 2 + 1];
#pragma unroll
                    for (int mi = 0; mi < 4; mi++)
                        mma_bf16(acc[mi][ni], afr[mi][0], afr[mi][1], afr[mi][2], afr[mi][3], b0, b1);
                }
        }
        __syncthreads();
    }

#pragma unroll
    for (int mi = 0; mi < 4; mi++) {
#pragma unroll
        for (int ni = 0; ni < 4; ni++) {
            int r0 = bm + mBase + mi * 16 + grp;
            int c0 = bn + nBase + ni * 8 + tig * 2;
            float bv0 = (bias && c0     < N) ? bias[c0]     : 0.f;
            float bv1 = (bias && c0 + 1 < N) ? bias[c0 + 1] : 0.f;
            if (r0 < M) {
                if (c0     < N) C[(long)r0 * N + c0]     = acc[mi][ni][0] + bv0;
                if (c0 + 1 < N) C[(long)r0 * N + c0 + 1] = acc[mi][ni][1] + bv1;
            }
            int r1 = r0 + 8;
            if (r1 < M) {
                if (c0     < N) C[(long)r1 * N + c0]     = acc[mi][ni][2] + bv0;
                if (c0 + 1 < N) C[(long)r1 * N + c0 + 1] = acc[mi][ni][3] + bv1;
            }
        }
    }
}

// =====================================================================
// LSTM v3: fully warp-independent steps.
// - Warp w owns all 4 gates of hidden units r*32+4w..+3 (16 z-cols).
// - 8 HMMA chains of depth 4; in-warp shuffle transpose for gates.
// - h pushed via st.async with tx-counting double mbarriers: the data
//   IS the arrival. No __syncthreads / bar.sync / arrive fan-out in loop.
// =====================================================================
template<int BSUB, bool WRITE_HS>
__device__ __forceinline__ void lstm_body_tc(
    const float* __restrict__ Z, const uint2* __restrict__ Upk,
    void* __restrict__ OUT, int sbase, int dir, int zstride)
{
    constexpr unsigned TX = BSUB * 256 * 2;   // bytes of h arriving per CTA per step
    __shared__ __align__(16) unsigned short hb[2][16][264];  // 528B rows
    __shared__ __align__(16) unsigned long long mbar[2];

    const int tid = threadIdx.x;
    const int warp = tid >> 5, lane = tid & 31;
    const int tig = lane & 3, grp = lane >> 2;
    const unsigned r = ctarank();

    // resident U fragments (coalesced packed load)
    uint BF[16][2][2];
    {
        const uint2* up = Upk + (((int)r * 8 + warp) << 10) + lane;
#pragma unroll
        for (int kt = 0; kt < 16; kt++)
#pragma unroll
            for (int nt = 0; nt < 2; nt++) {
                uint2 v = up[(kt * 2 + nt) << 5];
                BF[kt][nt][0] = v.x;
                BF[kt][nt][1] = v.y;
            }
    }
    uint* hbw = (uint*)&hb[0][0][0];
    for (int i = tid; i < 2 * 16 * 132; i += 256) hbw[i] = 0;
    const unsigned mb_s = (unsigned)__cvta_generic_to_shared(&mbar[0]);
    if (tid == 0) {
        mbar_init(mb_s, 1);
        mbar_init(mb_s + 8, 1);
        mbar_expect(mb_s + 8, TX);   // arm for step-0 stores (wait at step 1)
        mbar_expect(mb_s,     TX);   // arm for step-1 stores (wait at step 2)
    }
    __syncthreads();
    cluster_sync_all();              // barriers + zeroed h visible cluster-wide

    const unsigned hb_s = (unsigned)__cvta_generic_to_shared(&hb[0][0][0]);
    unsigned rhb[8], rmb[8];
#pragma unroll
    for (int tr = 0; tr < 8; tr++) {
        rhb[tr] = mapa_addr(hb_s, (unsigned)tr);
        rmb[tr] = mapa_addr(mb_s, (unsigned)tr);
    }

    const bool valid = grp < BSUB;
    const int gcol = (int)r * 32 + warp * 4 + tig;    // global hidden unit
    float cst = 0.f;
    const float* zr0 = Z + (long)(sbase + grp) * Tn * zstride + gcol;

    float zin[4];
    if (valid) {
        const float* zr = zr0 + (long)(dir ? Tn - 1 : 0) * zstride;
#pragma unroll
        for (int g = 0; g < 4; g++) zin[g] = zr[g << 8];
    }

    int par0 = 0, par1 = 0;
    for (int step = 0; step < Tn; ++step) {
        const int cur = step & 1, nxt = cur ^ 1;
        const int t = dir ? (Tn - 1 - step) : step;

        // prefetch NEXT step's z (full step of latency cover)
        float znx[4];
        if (valid && step + 1 < Tn) {
            const float* zr = zr0 + (long)(dir ? Tn - 2 - step : step + 1) * zstride;
#pragma unroll
            for (int g = 0; g < 4; g++) znx[g] = zr[g << 8];
        }

        if (step > 0) {
            const int b = step & 1;
            mbar_wait(mb_s + b * 8, (unsigned)(b ? par1 : par0));
            if (b) par1 ^= 1; else par0 ^= 1;
            if (tid == 0 && step + 2 < Tn) mbar_expect(mb_s + b * 8, TX);  // re-arm
        }

        // ---- z = h @ U : 8 independent 4-deep HMMA chains ----
        float acc[8][4];
#pragma unroll
        for (int i = 0; i < 8; i++)
#pragma unroll
            for (int j = 0; j < 4; j++) acc[i][j] = 0.f;
        unsigned hrow = hb_s + (unsigned)((cur * 16 + (lane & 15)) * 528)
                             + (unsigned)((lane >> 4) << 4);
#pragma unroll
        for (int kt = 0; kt < 16; kt++) {
            uint x0, x1, x2, x3;
            ldsm_x4(x0, x1, x2, x3, hrow + (unsigned)(kt * 32));
            mma_bf16(acc[kt & 3],       x0, x1, x2, x3, BF[kt][0][0], BF[kt][0][1]);
            mma_bf16(acc[4 + (kt & 3)], x0, x1, x2, x3, BF[kt][1][0], BF[kt][1][1]);
        }
        float A0 = acc[0][0] + acc[1][0] + acc[2][0] + acc[3][0];
        float A1 = acc[0][1] + acc[1][1] + acc[2][1] + acc[3][1];
        float B0 = acc[4][0] + acc[5][0] + acc[6][0] + acc[7][0];
        float B1 = acc[4][1] + acc[5][1] + acc[6][1] + acc[7][1];

        // ---- in-warp gate transpose (8 SHFL) ----
        float rA0 = __shfl_xor_sync(0xffffffffu, A0, 1);
        float rA1 = __shfl_xor_sync(0xffffffffu, A1, 1);
        float rB0 = __shfl_xor_sync(0xffffffffu, B0, 1);
        float rB1 = __shfl_xor_sync(0xffffffffu, B1, 1);
        const bool oddt = tig & 1;
        float gA0 = oddt ? rA0 : A0, gA1 = oddt ? rA1 : A1;
        float gA2 = oddt ? A0 : rA0, gA3 = oddt ? A1 : rA1;
        float gB0 = oddt ? rB0 : B0, gB1 = oddt ? rB1 : B1;
        float gB2 = oddt ? B0 : rB0, gB3 = oddt ? B1 : rB1;
        const bool hiA = (tig & 2) != 0;           // lanes tig 2,3 send gA; 0,1 send gB
        float v0 = hiA ? gA0 : gB0, v1 = hiA ? gA1 : gB1;
        float v2 = hiA ? gA2 : gB2, v3 = hiA ? gA3 : gB3;
        float w0 = __shfl_xor_sync(0xffffffffu, v0, 2);
        float w1 = __shfl_xor_sync(0xffffffffu, v1, 2);
        float w2 = __shfl_xor_sync(0xffffffffu, v2, 2);
        float w3 = __shfl_xor_sync(0xffffffffu, v3, 2);
        float gz0 = (tig == 0) ? gA0 : (tig == 3) ? gB0 : w0;
        float gz1 = (tig == 0) ? gA1 : (tig == 3) ? gB1 : w1;
        float gz2 = (tig == 0) ? gA2 : (tig == 3) ? gB2 : w2;
        float gz3 = (tig == 0) ? gA3 : (tig == 3) ? gB3 : w3;

        // ---- cell update (1 unit per lane: sample grp, unit gcol) ----
        float zi = gz0 + zin[0];
        float zf = gz1 + zin[1];
        float zg = gz2 + zin[2];
        float zo = gz3 + zin[3];
        cst = sigmoidf_(zf) * cst + sigmoidf_(zi) * fmaxf(zg, 0.f);
        float h = sigmoidf_(zo) * fmaxf(cst, 0.f);
        float hp = __shfl_xor_sync(0xffffffffu, h, 1);
        uint hv = pack2bf(h, hp);                  // valid on even tig

        if (WRITE_HS) {
            if (valid && !oddt)
                *(uint*)((__nv_bfloat16*)OUT +
                         ((long)(sbase + grp) * Tn + t) * 512 + dir * 256 + gcol) = hv;
        } else if (step == Tn - 1) {
            if (valid)
                ((float*)OUT)[(sbase + grp) * 256 + gcol] = h;
        }

        // ---- push h(step+1) to all ranks via st.async (data = signal) ----
        if (step < Tn - 1 && valid && !oddt) {
            unsigned off = (unsigned)((nxt * 16 + grp) * 528 + (gcol << 1));
            unsigned mboff = (unsigned)(nxt * 8);
#pragma unroll
            for (int tr = 0; tr < 8; tr++)
                st_async_u32(rhb[tr] + off, hv, rmb[tr] + mboff);
        }
#pragma unroll
        for (int g = 0; g < 4; g++) zin[g] = znx[g];
    }
    cluster_sync_all();
    if (tid == 0) { mbar_inval(mb_s); mbar_inval(mb_s + 8); }
}

__global__ void __cluster_dims__(8, 1, 1) __launch_bounds__(256, 1)
lstm1_kernel(const float* __restrict__ Zcat, const uint2* __restrict__ Upk,
             __nv_bfloat16* __restrict__ HS)
{
    int cid = blockIdx.x >> 3;
    int dir = cid >> 3;
    int cl  = cid & 7;
    lstm_body_tc<8, true>(Zcat + dir * 1024, Upk + dir * 65536, HS, cl * 8, dir, 2048);
}

__global__ void __cluster_dims__(8, 1, 1) __launch_bounds__(256, 1)
lstm2_kernel(const float* __restrict__ Z, const uint2* __restrict__ Upk,
             float* __restrict__ HL)
{
    int cid = blockIdx.x >> 3;
    lstm_body_tc<4, false>(Z, Upk + 2 * 65536, HL, cid * 4, 0, 1024);
}

// =====================================================================
// Dense head + softmax
// =====================================================================
__global__ __launch_bounds__(256) void dense3_kernel(
    const float* __restrict__ HL, const float* __restrict__ W3,
    const float* __restrict__ b3, __nv_bfloat16* __restrict__ D3bf)
{
    __shared__ float h[256];
    int s = blockIdx.x;
    h[threadIdx.x] = HL[s * 256 + threadIdx.x];
    __syncthreads();
    for (int j = threadIdx.x; j < U3n; j += 256) {
        float acc = b3[j];
#pragma unroll 8
        for (int k = 0; k < 256; k++) acc = fmaf(h[k], W3[k * U3n + j], acc);
        D3bf[s * U3n + j] = __float2bfloat16_rn(fmaxf(acc, 0.f));
    }
}

__global__ __launch_bounds__(256) void softmax_kernel(float* __restrict__ X)
{
    __shared__ float red[256];
    float* x = X + (long)blockIdx.x * U4n;
    int tid = threadIdx.x;

    float m = -1e30f;
    for (int j = tid; j < U4n; j += 256) m = fmaxf(m, x[j]);
    red[tid] = m; __syncthreads();
    for (int s = 128; s > 0; s >>= 1) {
        if (tid < s) red[tid] = fmaxf(red[tid], red[tid + s]);
        __syncthreads();
    }
    m = red[0]; __syncthreads();

    float sum = 0.f;
    for (int j = tid; j < U4n; j += 256) {
        float e = __expf(x[j] - m);
        x[j] = e;
        sum += e;
    }
    red[tid] = sum; __syncthreads();
    for (int s = 128; s > 0; s >>= 1) {
        if (tid < s) red[tid] += red[tid + s];
        __syncthreads();
    }
    float inv = 1.f / red[0];
    __syncthreads();
    for (int j = tid; j < U4n; j += 256) x[j] *= inv;
}

// =====================================================================
// launcher
// =====================================================================
extern "C" void kernel_launch(void* const* d_in, const int* in_sizes, int n_in,
                              void* d_out, int out_size)
{
    const int*   tokens = (const int*)  d_in[0];
    const float* emb    = (const float*)d_in[1];
    const float* W1f    = (const float*)d_in[2];
    const float* U1f    = (const float*)d_in[3];
    const float* b1f    = (const float*)d_in[4];
    const float* W1b    = (const float*)d_in[5];
    const float* U1b    = (const float*)d_in[6];
    const float* b1b    = (const float*)d_in[7];
    const float* W2     = (const float*)d_in[8];
    const float* U2m    = (const float*)d_in[9];
    const float* b2     = (const float*)d_in[10];
    const float* W3     = (const float*)d_in[11];
    const float* b3     = (const float*)d_in[12];
    const float* W4     = (const float*)d_in[13];
    const float* b4     = (const float*)d_in[14];
    float* out = (float*)d_out;

    float *Z1cat, *Z2, *HL, *bcat;
    __nv_bfloat16 *HS, *D3bf, *Xbf, *W1cat, *W2_bf, *W4_bf;
    uint2* Upk;
    cudaGetSymbolAddress((void**)&Z1cat, g_Z1cat);
    cudaGetSymbolAddress((void**)&Z2,    g_Z2);
    cudaGetSymbolAddress((void**)&HS,    g_HS);
    cudaGetSymbolAddress((void**)&HL,    g_HL);
    cudaGetSymbolAddress((void**)&D3bf,  g_D3bf);
    cudaGetSymbolAddress((void**)&Xbf,   g_Xbf);
    cudaGetSymbolAddress((void**)&W1cat, g_W1cat);
    cudaGetSymbolAddress((void**)&bcat,  g_bcat);
    cudaGetSymbolAddress((void**)&W2_bf, g_W2_bf);
    cudaGetSymbolAddress((void**)&W4_bf, g_W4_bf);
    cudaGetSymbolAddress((void**)&Upk,   g_Upk);

    cudaFuncSetAttribute((const void*)gemm_bf16_v3,
                         cudaFuncAttributeMaxDynamicSharedMemorySize, GEMM_SMEM);

    // 0: fused gather+convert of used embedding rows
    gatherconv_kernel<<<2048, 256>>>(emb, tokens, Xbf);
    // 1: all weight prep for LSTM1/LSTM2 (W1cat, bcat, packed U tables)
    prep_kernel<<<1024, 256>>>(W1f, W1b, b1f, b1b, U1f, U1b, U2m, W1cat, bcat, Upk);
    // 2: fused LSTM1 input projection (fw|bw)
    {
        dim3 grid(16, 128);
        gemm_bf16_v3<<<grid, 256, GEMM_SMEM>>>(Xbf, W1cat, bcat, Z1cat,
                                               ROWS, 2048, En, En);
    }
    // 3: BiLSTM layer 1  (profiled launch)
    lstm1_kernel<<<128, 256>>>(Z1cat, Upk, HS);
    // 4,5: head weight conversions (consumed at launches 6 and 9)
    f2bf_kernel<<<512,  256>>>(W2, W2_bf, 512 * 1024 / 4);
    f2bf_kernel<<<1024, 256>>>(W4, W4_bf, 512 * U4n / 4);
    // 6: LSTM2 input projection
    {
        dim3 grid(8, 128);
        gemm_bf16_v3<<<grid, 256, GEMM_SMEM>>>(HS, W2_bf, b2, Z2,
                                               ROWS, 1024, 512, 512);
    }
    // 7: LSTM2 (h_last only)
    lstm2_kernel<<<128, 256>>>(Z2, Upk, HL);
    // 8: dense relu -> bf16
    dense3_kernel<<<Bn, 256>>>(HL, W3, b3, D3bf);
    // 9: logits GEMM into d_out
    {
        dim3 grid((U4n + 127) / 128, 1);
        gemm_bf16_v3<<<grid, 256, GEMM_SMEM>>>(D3bf, W4_bf, b4, out,
                                               Bn, U4n, U3n, U3n);
    }
    // 10: softmax in place
    softmax_kernel<<<Bn, 256>>>(out);
}

// round 8
// speedup vs baseline: 3.2977x; 1.1914x over previous
#include <cuda_runtime.h>
#include <cuda_bf16.h>
#include <cstdint>

typedef unsigned int uint;

// ---------------- problem constants ----------------
#define Bn   64
#define Tn   256
#define En   128
#define H1   256
#define H2   256
#define U3n  512
#define U4n  5000
#define ROWS (Bn*Tn)      // 16384

// ---------------- scratch ----------------
__device__ float g_Z1cat[ROWS * 2048];            // fw cols 0..1023, bw 1024..2047
__device__ float g_Z2 [ROWS * 1024];
__device__ __nv_bfloat16 g_HS[ROWS * 512];
__device__ float g_HL [Bn * H2];
__device__ __nv_bfloat16 g_D3bf[Bn * U3n];
__device__ __nv_bfloat16 g_Xbf[ROWS * En];        // gathered+converted embeddings
__device__ __nv_bfloat16 g_W1cat[En * 2048];
__device__ float g_bcat[2048];
__device__ __nv_bfloat16 g_W2_bf [512 * 1024];
__device__ __nv_bfloat16 g_W4_bf [512 * U4n];
__device__ uint2 g_Upk[3 * 65536];                // packed U frags: U1f, U1b, U2m

// ---------------- helpers ----------------
__device__ __forceinline__ unsigned ctarank() {
    unsigned r; asm("mov.u32 %0, %%cluster_ctarank;" : "=r"(r)); return r;
}
__device__ __forceinline__ void cluster_sync_all() {
    asm volatile("barrier.cluster.arrive.aligned;\n\tbarrier.cluster.wait.aligned;" ::: "memory");
}
__device__ __forceinline__ unsigned mapa_addr(unsigned a, unsigned rank) {
    unsigned ra;
    asm volatile("mapa.shared::cluster.u32 %0, %1, %2;" : "=r"(ra) : "r"(a), "r"(rank));
    return ra;
}
__device__ __forceinline__ void bulk_s2s(unsigned dst, unsigned src, unsigned bytes, unsigned mb) {
    asm volatile("cp.async.bulk.shared::cluster.shared::cta.mbarrier::complete_tx::bytes "
                 "[%0], [%1], %2, [%3];"
                 :: "r"(dst), "r"(src), "r"(bytes), "r"(mb) : "memory");
}
__device__ __forceinline__ void fence_proxy_async_cta() {
    asm volatile("fence.proxy.async.shared::cta;" ::: "memory");
}
__device__ __forceinline__ void mbar_init(unsigned mb, unsigned cnt) {
    asm volatile("mbarrier.init.shared.b64 [%0], %1;" :: "r"(mb), "r"(cnt) : "memory");
}
__device__ __forceinline__ void mbar_inval(unsigned mb) {
    asm volatile("mbarrier.inval.shared.b64 [%0];" :: "r"(mb) : "memory");
}
__device__ __forceinline__ void mbar_expect(unsigned mb, unsigned tx) {
    asm volatile("mbarrier.arrive.expect_tx.shared.b64 _, [%0], %1;" :: "r"(mb), "r"(tx) : "memory");
}
__device__ __forceinline__ void mbar_wait(unsigned addr, unsigned parity) {
    asm volatile(
        "{\n\t.reg .pred P;\n"
        "LW_%=:\n\t"
        "mbarrier.try_wait.parity.acquire.cluster.shared::cta.b64 P, [%0], %1;\n\t"
        "@P bra LD_%=;\n\t"
        "bra LW_%=;\n"
        "LD_%=:\n\t}"
        :: "r"(addr), "r"(parity) : "memory");
}
__device__ __forceinline__ uint pack2bf(float a, float b) {
    __nv_bfloat162 t = __floats2bfloat162_rn(a, b);
    return *(uint*)&t;
}
__device__ __forceinline__ void mma_bf16(float* d,
                                         uint a0, uint a1, uint a2, uint a3,
                                         uint b0, uint b1) {
    asm volatile("mma.sync.aligned.m16n8k16.row.col.f32.bf16.bf16.f32 "
                 "{%0,%1,%2,%3},{%4,%5,%6,%7},{%8,%9},{%0,%1,%2,%3};"
                 : "+f"(d[0]), "+f"(d[1]), "+f"(d[2]), "+f"(d[3])
                 : "r"(a0), "r"(a1), "r"(a2), "r"(a3), "r"(b0), "r"(b1));
}
__device__ __forceinline__ void ldsm_x4(uint& r0, uint& r1, uint& r2, uint& r3, unsigned a) {
    asm volatile("ldmatrix.sync.aligned.m8n8.x4.shared.b16 {%0,%1,%2,%3}, [%4];"
                 : "=r"(r0), "=r"(r1), "=r"(r2), "=r"(r3) : "r"(a));
}
__device__ __forceinline__ void ldsm_x4t(uint& r0, uint& r1, uint& r2, uint& r3, unsigned a) {
    asm volatile("ldmatrix.sync.aligned.m8n8.x4.trans.shared.b16 {%0,%1,%2,%3}, [%4];"
                 : "=r"(r0), "=r"(r1), "=r"(r2), "=r"(r3) : "r"(a));
}
__device__ __forceinline__ void cp_async16(unsigned saddr, const void* gaddr) {
    asm volatile("cp.async.cg.shared.global [%0], [%1], 16;" :: "r"(saddr), "l"(gaddr));
}
__device__ __forceinline__ float sigmoidf_(float z) {
    return 1.0f / (1.0f + __expf(-z));
}

// =====================================================================
// Fused gather + f32->bf16: Xbf[i,:] = bf16(emb[tokens[i],:])
// =====================================================================
__global__ __launch_bounds__(256) void gatherconv_kernel(
    const float* __restrict__ emb, const int* __restrict__ tokens,
    __nv_bfloat16* __restrict__ Xbf)
{
    int u = blockIdx.x * 256 + threadIdx.x;
    int row = u >> 5;
    int c4 = (u & 31) << 2;
    long tok = tokens[row];
    float4 v = *(const float4*)&emb[tok * En + c4];
    uint2 w;
    w.x = pack2bf(v.x, v.y);
    w.y = pack2bf(v.z, v.w);
    *(uint2*)&Xbf[(long)row * En + c4] = w;
}

// =====================================================================
// Prep: W1cat concat+convert (+bcat) and packed-U fragment tables.
// Fragment column mapping (warp-local gate ownership), same as round 7:
//   local col cc = nt*8 + grp  ->  global col (cc&3)*256 + r*32 + w*4 + (cc>>2)
// =====================================================================
__global__ __launch_bounds__(256) void prep_kernel(
    const float* __restrict__ W1f, const float* __restrict__ W1b,
    const float* __restrict__ b1f, const float* __restrict__ b1b,
    const float* __restrict__ U1f, const float* __restrict__ U1b,
    const float* __restrict__ U2m,
    __nv_bfloat16* __restrict__ Wcat, float* __restrict__ bcat,
    uint2* __restrict__ Upk)
{
    int bid = blockIdx.x;
    if (bid < 256) {
        int u = bid * 256 + threadIdx.x;
        int row = u >> 9;
        int c4 = (u & 511) << 2;
        const float* src = (c4 < 1024) ? &W1f[row * 1024 + c4]
                                       : &W1b[row * 1024 + c4 - 1024];
        float4 v = *(const float4*)src;
        uint2 w;
        w.x = pack2bf(v.x, v.y);
        w.y = pack2bf(v.z, v.w);
        *(uint2*)&Wcat[(long)row * 2048 + c4] = w;
        if (bid == 0) {
            for (int j = threadIdx.x; j < 1024; j += 256) {
                bcat[j] = b1f[j];
                bcat[1024 + j] = b1b[j];
            }
        }
    } else {
        int g = (bid - 256) * 256 + threadIdx.x;
        int which = g >> 16;
        int idx = g & 65535;
        int lane = idx & 31;
        int rest = idx >> 5;
        int nt = rest & 1;
        int kt = (rest >> 1) & 15;
        int w  = (rest >> 5) & 7;
        int r  = rest >> 8;
        const float* U = (which == 0) ? U1f : (which == 1) ? U1b : U2m;
        int tig = lane & 3, grp = lane >> 2;
        int cc = nt * 8 + grp;
        int c = (cc & 3) * 256 + r * 32 + w * 4 + (cc >> 2);
        int k0 = kt * 16 + tig * 2;
        uint2 v;
        v.x = pack2bf(U[(long)(k0    ) * 1024 + c], U[(long)(k0 + 1) * 1024 + c]);
        v.y = pack2bf(U[(long)(k0 + 8) * 1024 + c], U[(long)(k0 + 9) * 1024 + c]);
        Upk[g] = v;
    }
}

// =====================================================================
// f32 -> bf16 conversion (vectorized, grid-stride). n % 4 == 0.
// =====================================================================
__global__ __launch_bounds__(256) void f2bf_kernel(
    const float* __restrict__ s, __nv_bfloat16* __restrict__ d, int n4)
{
    int i = blockIdx.x * blockDim.x + threadIdx.x;
    int stride = gridDim.x * blockDim.x;
    for (; i < n4; i += stride) {
        float4 v = ((const float4*)s)[i];
        uint2 w;
        w.x = pack2bf(v.x, v.y);
        w.y = pack2bf(v.z, v.w);
        ((uint2*)d)[i] = w;
    }
}

// =====================================================================
// bf16 GEMM v3 (unchanged): 3-stage cp.async pipeline + ldmatrix.
// =====================================================================
#define A_STG 18432
#define B_STG 17408
#define B_OFF 55296
#define GEMM_SMEM 107520

__global__ __launch_bounds__(256) void gemm_bf16_v3(
    const __nv_bfloat16* __restrict__ A, const __nv_bfloat16* __restrict__ B,
    const float* __restrict__ bias, float* __restrict__ C,
    int M, int N, int K, int lda)
{
    extern __shared__ char dynsm[];
    const unsigned sbase = (unsigned)__cvta_generic_to_shared(dynsm);

    const int bm = blockIdx.y * 128;
    const int bn = blockIdx.x * 128;
    const int tid = threadIdx.x;
    const int warp = tid >> 5, lane = tid & 31;
    const int wm = warp >> 2, wn = warp & 3;
    const int mBase = wm * 64, nBase = wn * 32;
    const int grp = lane >> 2, tig = lane & 3;

    auto stage = [&](int kb, int st) {
#pragma unroll
        for (int i = 0; i < 4; i++) {
            int idx = tid + i * 256;
            int row = idx >> 3, ch = idx & 7;
            unsigned off = (unsigned)(st * A_STG + row * 144 + ch * 16);
            if (bm + row < M) {
                cp_async16(sbase + off, A + (long)(bm + row) * lda + kb * 64 + ch * 8);
            } else {
                *(uint4*)(dynsm + off) = make_uint4(0, 0, 0, 0);
            }
        }
#pragma unroll
        for (int i = 0; i < 4; i++) {
            int idx = tid + i * 256;
            int k = idx >> 4, ch = idx & 15;
            int gc = bn + ch * 8;
            unsigned off = (unsigned)(B_OFF + st * B_STG + k * 272 + ch * 16);
            if (gc < N) {
                cp_async16(sbase + off, B + (long)(kb * 64 + k) * N + gc);
            } else {
                *(uint4*)(dynsm + off) = make_uint4(0, 0, 0, 0);
            }
        }
        asm volatile("cp.async.commit_group;");
    };

    float acc[4][4][4];
#pragma unroll
    for (int a = 0; a < 4; a++)
#pragma unroll
        for (int b = 0; b < 4; b++)
#pragma unroll
            for (int c = 0; c < 4; c++) acc[a][b][c] = 0.f;

    const int nk = K >> 6;
    stage(0, 0);
    if (nk > 1) stage(1, 1);

    for (int kb = 0; kb < nk; kb++) {
        int st = kb % 3;
        if (kb + 2 < nk) {
            stage(kb + 2, (kb + 2) % 3);
            asm volatile("cp.async.wait_group 2;");
        } else if (kb + 1 < nk) {
            asm volatile("cp.async.wait_group 1;");
        } else {
            asm volatile("cp.async.wait_group 0;");
        }
        __syncthreads();

        unsigned aRow = sbase + (unsigned)(st * A_STG)
                      + (unsigned)((mBase + (lane & 15)) * 144)
                      + (unsigned)((lane >> 4) << 4);
        unsigned bCol = sbase + (unsigned)(B_OFF + st * B_STG)
                      + (unsigned)((lane & 15) * 272)
                      + (unsigned)(nBase * 2 + ((lane >> 4) << 4));

#pragma unroll
        for (int kt = 0; kt < 4; kt++) {
            uint afr[4][4];
#pragma unroll
            for (int mi = 0; mi < 4; mi++)
                ldsm_x4(afr[mi][0], afr[mi][1], afr[mi][2], afr[mi][3],
                        aRow + (unsigned)(mi * 16 * 144 + kt * 32));
            uint bfr[2][4];
#pragma unroll
            for (int nh = 0; nh < 2; nh++)
                ldsm_x4t(bfr[nh][0], bfr[nh][1], bfr[nh][2], bfr[nh][3],
                         bCol + (unsigned)(kt * 16 * 272 + nh * 32));
#pragma unroll
            for (int nh = 0; nh < 2; nh++)
#pragma unroll
                for (int hf = 0; hf < 2; hf++) {
                    int ni = nh * 2 + hf;
                    uint b0 = bfr[nh][hf * 2], b1 = bfr[nh][hf * 2 + 1];
#pragma unroll
                    for (int mi = 0; mi < 4; mi++)
                        mma_bf16(acc[mi][ni], afr[mi][0], afr[mi][1], afr[mi][2], afr[mi][3], b0, b1);
                }
        }
        __syncthreads();
    }

#pragma unroll
    for (int mi = 0; mi < 4; mi++) {
#pragma unroll
        for (int ni = 0; ni < 4; ni++) {
            int r0 = bm + mBase + mi * 16 + grp;
            int c0 = bn + nBase + ni * 8 + tig * 2;
            float bv0 = (bias && c0     < N) ? bias[c0]     : 0.f;
            float bv1 = (bias && c0 + 1 < N) ? bias[c0 + 1] : 0.f;
            if (r0 < M) {
                if (c0     < N) C[(long)r0 * N + c0]     = acc[mi][ni][0] + bv0;
                if (c0 + 1 < N) C[(long)r0 * N + c0 + 1] = acc[mi][ni][1] + bv1;
            }
            int r1 = r0 + 8;
            if (r1 < M) {
                if (c0     < N) C[(long)r1 * N + c0]     = acc[mi][ni][2] + bv0;
                if (c0 + 1 < N) C[(long)r1 * N + c0 + 1] = acc[mi][ni][3] + bv1;
            }
        }
    }
}

// =====================================================================
// LSTM v4: bulk-aggregated h exchange.
// - warp-gate ownership + shuffle transpose (round 7, unchanged math)
// - h exchange: per-warp 64B -> staging 512B -> ONE cp.async.bulk 512B
//   per peer rank (8 bulk copies, 8 tx-updates per barrier per step)
// - recv layout [srcRank][sample][64B] with chunk-XOR(s>>1) permutation
//   -> conflict-free ldmatrix rows
// - Z prefetched 2 steps ahead
// =====================================================================
template<int BSUB, bool WRITE_HS>
__device__ __forceinline__ void lstm_body_tc(
    const float* __restrict__ Z, const uint2* __restrict__ Upk,
    void* __restrict__ OUT, int sbase, int dir, int zstride)
{
    constexpr unsigned TX = 8 * 512;  // bytes arriving per CTA per step
    __shared__ __align__(16) char hrecv[2][4096];   // [par][rank][sample][64B]
    __shared__ __align__(16) char stg[2][512];      // [par][sample][64B] (permuted)
    __shared__ __align__(16) uint zblk[4];          // 16B zeros for pad rows
    __shared__ __align__(8) unsigned long long mbar[2];

    const int tid = threadIdx.x;
    const int warp = tid >> 5, lane = tid & 31;
    const int tig = lane & 3, grp = lane >> 2;
    const unsigned r = ctarank();

    // resident U fragments (coalesced packed load)
    uint BF[16][2][2];
    {
        const uint2* up = Upk + (((int)r * 8 + warp) << 10) + lane;
#pragma unroll
        for (int kt = 0; kt < 16; kt++)
#pragma unroll
            for (int nt = 0; nt < 2; nt++) {
                uint2 v = up[(kt * 2 + nt) << 5];
                BF[kt][nt][0] = v.x;
                BF[kt][nt][1] = v.y;
            }
    }
    // zero hrecv[0] (initial h=0) and zero block
    for (int i = tid; i < 1024; i += 256) ((uint*)&hrecv[0][0])[i] = 0;
    if (tid < 4) zblk[tid] = 0;

    const unsigned mb_s   = (unsigned)__cvta_generic_to_shared(&mbar[0]);
    const unsigned hr_s   = (unsigned)__cvta_generic_to_shared(&hrecv[0][0]);
    const unsigned stg_s  = (unsigned)__cvta_generic_to_shared(&stg[0][0]);
    const unsigned zb_s   = (unsigned)__cvta_generic_to_shared(&zblk[0]);
    if (tid == 0) {
        mbar_init(mb_s, 1);
        mbar_init(mb_s + 8, 1);
        mbar_expect(mb_s + 8, TX);   // phase completing at step-1 wait
        mbar_expect(mb_s,     TX);   // phase completing at step-2 wait
    }
    __syncthreads();
    cluster_sync_all();

    // per-warp remote targets (rank = warp)
    const unsigned rdst = mapa_addr(hr_s, (unsigned)warp);
    const unsigned rmb  = mapa_addr(mb_s, (unsigned)warp);

    // ldsm row addressing (conflict-free permuted layout)
    const int s15 = lane & 15, hf = lane >> 4;
    const int xr = (s15 >> 1) & 3;
    const unsigned ce = (unsigned)(((hf    ) ^ xr) << 4);
    const unsigned co = (unsigned)(((2 + hf) ^ xr) << 4);
    const unsigned rowoff = (unsigned)(s15 * 64);
    const bool srow = s15 < 8;

    // staging write address (even-tig lanes store packed pair)
    const unsigned stw = stg_s
        + (unsigned)(grp * 64 + (((warp >> 1) ^ ((grp >> 1) & 3)) << 4)
                     + (warp & 1) * 8 + tig * 2);

    const bool valid = grp < BSUB;
    const bool oddt = tig & 1;
    const int gcol = (int)r * 32 + warp * 4 + tig;
    float cst = 0.f;
    const float* zr0 = Z + (long)(sbase + grp) * Tn * zstride + gcol;

    float zin[4], zn1[4];
    if (valid) {
        const float* za = zr0 + (long)(dir ? Tn - 1 : 0) * zstride;
        const float* zb = zr0 + (long)(dir ? Tn - 2 : 1) * zstride;
#pragma unroll
        for (int g = 0; g < 4; g++) { zin[g] = za[g << 8]; zn1[g] = zb[g << 8]; }
    }

    int par0 = 0, par1 = 0;
    for (int step = 0; step < Tn; ++step) {
        const int cur = step & 1, nxt = cur ^ 1;
        const int t = dir ? (Tn - 1 - step) : step;

        // prefetch z two steps ahead
        float zn2[4];
        if (valid && step + 2 < Tn) {
            const float* zr = zr0 + (long)(dir ? Tn - 3 - step : step + 2) * zstride;
#pragma unroll
            for (int g = 0; g < 4; g++) zn2[g] = zr[g << 8];
        }

        if (step > 0) {
            mbar_wait(mb_s + cur * 8, (unsigned)(cur ? par1 : par0));
            if (cur) par1 ^= 1; else par0 ^= 1;
            if (tid == 0 && step + 2 < Tn) mbar_expect(mb_s + cur * 8, TX);
        }

        // ---- z = h @ U : 8 independent 4-deep HMMA chains ----
        float acc[8][4];
#pragma unroll
        for (int i = 0; i < 8; i++)
#pragma unroll
            for (int j = 0; j < 4; j++) acc[i][j] = 0.f;
        const unsigned hb_p = hr_s + (unsigned)(cur * 4096);
#pragma unroll
        for (int kt = 0; kt < 16; kt++) {
            unsigned a = srow
                ? (hb_p + (unsigned)((kt >> 1) << 9) + rowoff + ((kt & 1) ? co : ce))
                : zb_s;
            uint x0, x1, x2, x3;
            ldsm_x4(x0, x1, x2, x3, a);
            mma_bf16(acc[kt & 3],       x0, x1, x2, x3, BF[kt][0][0], BF[kt][0][1]);
            mma_bf16(acc[4 + (kt & 3)], x0, x1, x2, x3, BF[kt][1][0], BF[kt][1][1]);
        }
        float A0 = acc[0][0] + acc[1][0] + acc[2][0] + acc[3][0];
        float A1 = acc[0][1] + acc[1][1] + acc[2][1] + acc[3][1];
        float B0 = acc[4][0] + acc[5][0] + acc[6][0] + acc[7][0];
        float B1 = acc[4][1] + acc[5][1] + acc[6][1] + acc[7][1];

        // ---- in-warp gate transpose ----
        float rA0 = __shfl_xor_sync(0xffffffffu, A0, 1);
        float rA1 = __shfl_xor_sync(0xffffffffu, A1, 1);
        float rB0 = __shfl_xor_sync(0xffffffffu, B0, 1);
        float rB1 = __shfl_xor_sync(0xffffffffu, B1, 1);
        float gA0 = oddt ? rA0 : A0, gA1 = oddt ? rA1 : A1;
        float gA2 = oddt ? A0 : rA0, gA3 = oddt ? A1 : rA1;
        float gB0 = oddt ? rB0 : B0, gB1 = oddt ? rB1 : B1;
        float gB2 = oddt ? B0 : rB0, gB3 = oddt ? B1 : rB1;
        const bool hiA = (tig & 2) != 0;
        float v0 = hiA ? gA0 : gB0, v1 = hiA ? gA1 : gB1;
        float v2 = hiA ? gA2 : gB2, v3 = hiA ? gA3 : gB3;
        float w0 = __shfl_xor_sync(0xffffffffu, v0, 2);
        float w1 = __shfl_xor_sync(0xffffffffu, v1, 2);
        float w2 = __shfl_xor_sync(0xffffffffu, v2, 2);
        float w3 = __shfl_xor_sync(0xffffffffu, v3, 2);
        float gz0 = (tig == 0) ? gA0 : (tig == 3) ? gB0 : w0;
        float gz1 = (tig == 0) ? gA1 : (tig == 3) ? gB1 : w1;
        float gz2 = (tig == 0) ? gA2 : (tig == 3) ? gB2 : w2;
        float gz3 = (tig == 0) ? gA3 : (tig == 3) ? gB3 : w3;

        // ---- cell update ----
        float zi = gz0 + zin[0];
        float zf = gz1 + zin[1];
        float zg = gz2 + zin[2];
        float zo = gz3 + zin[3];
        cst = sigmoidf_(zf) * cst + sigmoidf_(zi) * fmaxf(zg, 0.f);
        float h = sigmoidf_(zo) * fmaxf(cst, 0.f);
        float hp = __shfl_xor_sync(0xffffffffu, h, 1);
        uint hv = pack2bf(h, hp);                  // valid on even tig

        if (WRITE_HS) {
            if (valid && !oddt)
                *(uint*)((__nv_bfloat16*)OUT +
                         ((long)(sbase + grp) * Tn + t) * 512 + dir * 256 + gcol) = hv;
        } else if (step == Tn - 1) {
            if (valid)
                ((float*)OUT)[(sbase + grp) * 256 + gcol] = h;
        }

        // ---- aggregated exchange: stage 64B/warp, one 512B bulk per rank ----
        if (step < Tn - 1) {
            if (!oddt)
                asm volatile("st.shared.b32 [%0], %1;"
                             :: "r"(stw + (unsigned)(nxt * 512)), "r"(hv) : "memory");
            __syncthreads();
            if (lane == 0) {
                fence_proxy_async_cta();
                bulk_s2s(rdst + (unsigned)(nxt * 4096 + (int)r * 512),
                         stg_s + (unsigned)(nxt * 512),
                         512u,
                         rmb + (unsigned)(nxt * 8));
            }
        }
#pragma unroll
        for (int g = 0; g < 4; g++) { zin[g] = zn1[g]; zn1[g] = zn2[g]; }
    }
    cluster_sync_all();
    if (tid == 0) { mbar_inval(mb_s); mbar_inval(mb_s + 8); }
}

__global__ void __cluster_dims__(8, 1, 1) __launch_bounds__(256, 1)
lstm1_kernel(const float* __restrict__ Zcat, const uint2* __restrict__ Upk,
             __nv_bfloat16* __restrict__ HS)
{
    int cid = blockIdx.x >> 3;
    int dir = cid >> 3;
    int cl  = cid & 7;
    lstm_body_tc<8, true>(Zcat + dir * 1024, Upk + dir * 65536, HS, cl * 8, dir, 2048);
}

__global__ void __cluster_dims__(8, 1, 1) __launch_bounds__(256, 1)
lstm2_kernel(const float* __restrict__ Z, const uint2* __restrict__ Upk,
             float* __restrict__ HL)
{
    int cid = blockIdx.x >> 3;
    lstm_body_tc<4, false>(Z, Upk + 2 * 65536, HL, cid * 4, 0, 1024);
}

// =====================================================================
// Dense head + softmax
// =====================================================================
__global__ __launch_bounds__(256) void dense3_kernel(
    const float* __restrict__ HL, const float* __restrict__ W3,
    const float* __restrict__ b3, __nv_bfloat16* __restrict__ D3bf)
{
    __shared__ float h[256];
    int s = blockIdx.x;
    h[threadIdx.x] = HL[s * 256 + threadIdx.x];
    __syncthreads();
    for (int j = threadIdx.x; j < U3n; j += 256) {
        float acc = b3[j];
#pragma unroll 8
        for (int k = 0; k < 256; k++) acc = fmaf(h[k], W3[k * U3n + j], acc);
        D3bf[s * U3n + j] = __float2bfloat16_rn(fmaxf(acc, 0.f));
    }
}

__global__ __launch_bounds__(256) void softmax_kernel(float* __restrict__ X)
{
    __shared__ float red[256];
    float* x = X + (long)blockIdx.x * U4n;
    int tid = threadIdx.x;

    float m = -1e30f;
    for (int j = tid; j < U4n; j += 256) m = fmaxf(m, x[j]);
    red[tid] = m; __syncthreads();
    for (int s = 128; s > 0; s >>= 1) {
        if (tid < s) red[tid] = fmaxf(red[tid], red[tid + s]);
        __syncthreads();
    }
    m = red[0]; __syncthreads();

    float sum = 0.f;
    for (int j = tid; j < U4n; j += 256) {
        float e = __expf(x[j] - m);
        x[j] = e;
        sum += e;
    }
    red[tid] = sum; __syncthreads();
    for (int s = 128; s > 0; s >>= 1) {
        if (tid < s) red[tid] += red[tid + s];
        __syncthreads();
    }
    float inv = 1.f / red[0];
    __syncthreads();
    for (int j = tid; j < U4n; j += 256) x[j] *= inv;
}

// =====================================================================
// launcher
// =====================================================================
extern "C" void kernel_launch(void* const* d_in, const int* in_sizes, int n_in,
                              void* d_out, int out_size)
{
    const int*   tokens = (const int*)  d_in[0];
    const float* emb    = (const float*)d_in[1];
    const float* W1f    = (const float*)d_in[2];
    const float* U1f    = (const float*)d_in[3];
    const float* b1f    = (const float*)d_in[4];
    const float* W1b    = (const float*)d_in[5];
    const float* U1b    = (const float*)d_in[6];
    const float* b1b    = (const float*)d_in[7];
    const float* W2     = (const float*)d_in[8];
    const float* U2m    = (const float*)d_in[9];
    const float* b2     = (const float*)d_in[10];
    const float* W3     = (const float*)d_in[11];
    const float* b3     = (const float*)d_in[12];
    const float* W4     = (const float*)d_in[13];
    const float* b4     = (const float*)d_in[14];
    float* out = (float*)d_out;

    float *Z1cat, *Z2, *HL, *bcat;
    __nv_bfloat16 *HS, *D3bf, *Xbf, *W1cat, *W2_bf, *W4_bf;
    uint2* Upk;
    cudaGetSymbolAddress((void**)&Z1cat, g_Z1cat);
    cudaGetSymbolAddress((void**)&Z2,    g_Z2);
    cudaGetSymbolAddress((void**)&HS,    g_HS);
    cudaGetSymbolAddress((void**)&HL,    g_HL);
    cudaGetSymbolAddress((void**)&D3bf,  g_D3bf);
    cudaGetSymbolAddress((void**)&Xbf,   g_Xbf);
    cudaGetSymbolAddress((void**)&W1cat, g_W1cat);
    cudaGetSymbolAddress((void**)&bcat,  g_bcat);
    cudaGetSymbolAddress((void**)&W2_bf, g_W2_bf);
    cudaGetSymbolAddress((void**)&W4_bf, g_W4_bf);
    cudaGetSymbolAddress((void**)&Upk,   g_Upk);

    cudaFuncSetAttribute((const void*)gemm_bf16_v3,
                         cudaFuncAttributeMaxDynamicSharedMemorySize, GEMM_SMEM);

    // 0: fused gather+convert of used embedding rows
    gatherconv_kernel<<<2048, 256>>>(emb, tokens, Xbf);
    // 1: all weight prep for LSTM1/LSTM2 (W1cat, bcat, packed U tables)
    prep_kernel<<<1024, 256>>>(W1f, W1b, b1f, b1b, U1f, U1b, U2m, W1cat, bcat, Upk);
    // 2: fused LSTM1 input projection (fw|bw)
    {
        dim3 grid(16, 128);
        gemm_bf16_v3<<<grid, 256, GEMM_SMEM>>>(Xbf, W1cat, bcat, Z1cat,
                                               ROWS, 2048, En, En);
    }
    // 3: BiLSTM layer 1  (profiled launch)
    lstm1_kernel<<<128, 256>>>(Z1cat, Upk, HS);
    // 4,5: head weight conversions (consumed at launches 6 and 9)
    f2bf_kernel<<<512,  256>>>(W2, W2_bf, 512 * 1024 / 4);
    f2bf_kernel<<<1024, 256>>>(W4, W4_bf, 512 * U4n / 4);
    // 6: LSTM2 input projection
    {
        dim3 grid(8, 128);
        gemm_bf16_v3<<<grid, 256, GEMM_SMEM>>>(HS, W2_bf, b2, Z2,
                                               ROWS, 1024, 512, 512);
    }
    // 7: LSTM2 (h_last only)
    lstm2_kernel<<<128, 256>>>(Z2, Upk, HL);
    // 8: dense relu -> bf16
    dense3_kernel<<<Bn, 256>>>(HL, W3, b3, D3bf);
    // 9: logits GEMM into d_out
    {
        dim3 grid((U4n + 127) / 128, 1);
        gemm_bf16_v3<<<grid, 256, GEMM_SMEM>>>(D3bf, W4_bf, b4, out,
                                               Bn, U4n, U3n, U3n);
    }
    // 10: softmax in place
    softmax_kernel<<<Bn, 256>>>(out);
}